// round 15
// baseline (speedup 1.0000x reference)
#include <cuda_runtime.h>
#include <math.h>
#include <stdint.h>

#define MAXN 50048
#define MAXE 800256
typedef unsigned long long u64;

// ---------------- scratch (static device arrays; no cudaMalloc) ----------------
__device__ float g_h  [MAXN*128];
__device__ float g_x  [MAXN*3];
__device__ float g_hA [MAXN*128];
__device__ float g_hB [MAXN*128];
__device__ float g_agg[MAXN*128];
__device__ float g_cup[MAXN*3];
__device__ float g_eps[MAXN*3];
__device__ float g_deg[MAXN];
__device__ uint32_t g_wtf[550272];   // weights tf32, n-major [n][K]
__device__ int g_hist[MAXN];
__device__ int g_bsum[256];
__device__ int g_cursor[MAXN];
__device__ int g_eRowS[MAXE];
__device__ int g_eColS[MAXE];

// ---------------- helpers ----------------
__device__ __forceinline__ float tanh_ap(float x) {
    float t; asm("tanh.approx.f32 %0,%1;" : "=f"(t) : "f"(x)); return t;
}
__device__ __forceinline__ float silu(float x) {
    return 0.5f * x * (1.0f + tanh_ap(0.5f * x));
}
__device__ __forceinline__ uint32_t f2tf(float f) {
    uint32_t r; asm("cvt.rna.tf32.f32 %0, %1;" : "=r"(r) : "f"(f)); return r;
}
__device__ __forceinline__ uint32_t smem_u32(const void* p) {
    uint32_t a;
    asm("{ .reg .u64 t; cvta.to.shared.u64 t, %1; cvt.u32.u64 %0, t; }" : "=r"(a) : "l"(p));
    return a;
}
__device__ __forceinline__ void mma8(float d[4], uint32_t a0, uint32_t a1, uint32_t a2, uint32_t a3,
                                     uint32_t b0, uint32_t b1) {
    asm volatile(
        "mma.sync.aligned.m16n8k8.row.col.f32.tf32.tf32.f32 "
        "{%0,%1,%2,%3},{%4,%5,%6,%7},{%8,%9},{%0,%1,%2,%3};"
        : "+f"(d[0]), "+f"(d[1]), "+f"(d[2]), "+f"(d[3])
        : "r"(a0), "r"(a1), "r"(a2), "r"(a3), "r"(b0), "r"(b1));
}
__device__ __forceinline__ void ldsm4(uint32_t& r0, uint32_t& r1, uint32_t& r2, uint32_t& r3, uint32_t addr) {
    asm volatile("ldmatrix.sync.aligned.m8n8.x4.shared.b16 {%0,%1,%2,%3},[%4];"
        : "=r"(r0), "=r"(r1), "=r"(r2), "=r"(r3) : "r"(addr));
}
__device__ __forceinline__ void red1(float* p, float a) {
    asm volatile("red.global.add.f32 [%0],%1;" :: "l"(p), "f"(a) : "memory");
}
__device__ __forceinline__ void cpa16(uint32_t saddr, const void* g) {
    asm volatile("cp.async.ca.shared.global [%0], [%1], 16;" :: "r"(saddr), "l"(g));
}
#define CP_COMMIT() asm volatile("cp.async.commit_group;" ::: "memory")
#define CP_WAIT1()  asm volatile("cp.async.wait_group 1;" ::: "memory")
#define CP_WAIT0()  asm volatile("cp.async.wait_group 0;" ::: "memory")

#define NT 256
#define STRA 132
#define STRB 36
#define SA_BYTES (128*STRA*4)           // 67584
#define CHUNK_BYTES (128*STRB*4)        // 18432
#define SB0_OFF SA_BYTES
#define SB1_OFF (SA_BYTES + CHUNK_BYTES)
#define SMEM_AB (SA_BYTES + 2*CHUNK_BYTES)   // 104448

__device__ __forceinline__ void prefetch_chunk(uint32_t dstAddr, const uint32_t* __restrict__ src,
                                               int Ksrc, int c, int tid) {
#pragma unroll
    for (int i = 0; i < 4; i++) {
        int u = tid + i * NT;
        int nn = u >> 3, kq = u & 7;
        cpa16(dstAddr + (uint32_t)(nn * STRB + kq * 4) * 4, src + nn * Ksrc + c * 32 + kq * 4);
    }
    CP_COMMIT();
}

__device__ __forceinline__ void mma_chunk(uint32_t sAaddr, uint32_t sBaddr,
                                          int warpM, int warpN, int lane, int kbase,
                                          float acc[2][8][4]) {
    uint32_t aBase = sAaddr + (uint32_t)((warpM*32 + (lane & 7) + ((lane >> 3) & 1) * 8) * STRA
                                         + (lane >> 4) * 4 + kbase) * 4;
    uint32_t bBase = sBaddr + (uint32_t)((warpN*64 + (lane >> 3) * 8 + (lane & 7)) * STRB) * 4;
#pragma unroll
    for (int kk = 0; kk < 32; kk += 8) {
        uint32_t a[2][4], b[2][2][4];
#pragma unroll
        for (int mi = 0; mi < 2; mi++)
            ldsm4(a[mi][0], a[mi][1], a[mi][2], a[mi][3], aBase + (uint32_t)(mi * 16 * STRA + kk) * 4);
#pragma unroll
        for (int nh = 0; nh < 2; nh++)
#pragma unroll
            for (int kh = 0; kh < 2; kh++)
                ldsm4(b[nh][kh][0], b[nh][kh][1], b[nh][kh][2], b[nh][kh][3],
                      bBase + (uint32_t)(nh * 32 * STRB + kk + kh * 4) * 4);
#pragma unroll
        for (int mi = 0; mi < 2; mi++)
#pragma unroll
            for (int nh = 0; nh < 2; nh++)
#pragma unroll
                for (int j = 0; j < 4; j++)
                    mma8(acc[mi][nh * 4 + j], a[mi][0], a[mi][1], a[mi][2], a[mi][3],
                         b[nh][0][j], b[nh][1][j]);
    }
}
__device__ __forceinline__ void acc_zero(float acc[2][8][4]) {
#pragma unroll
    for (int mi = 0; mi < 2; mi++)
#pragma unroll
        for (int ni = 0; ni < 8; ni++)
#pragma unroll
            for (int j = 0; j < 4; j++) acc[mi][ni][j] = 0.0f;
}
__device__ __forceinline__ void pipe_gemm(uint32_t sAaddr, uint32_t sb0a, uint32_t sb1a,
    const uint32_t* __restrict__ W, int Ksrc, int nchunks, int tid,
    int warpM, int warpN, int lane, bool c0done, float acc[2][8][4])
{
    if (!c0done) prefetch_chunk(sb0a, W, Ksrc, 0, tid);
    for (int c = 0; c < nchunks; c++) {
        if (c + 1 < nchunks) {
            prefetch_chunk((c & 1) ? sb0a : sb1a, W, Ksrc, c + 1, tid);
            CP_WAIT1();
        } else {
            CP_WAIT0();
        }
        __syncthreads();
        mma_chunk(sAaddr, (c & 1) ? sb1a : sb0a, warpM, warpN, lane, c * 32, acc);
        __syncthreads();
    }
}

// ---------------- weight pre-conversion (transpose to n-major tf32) ----------------
struct CvtArgs { const float* src[34]; int off[34]; int K[34]; };
__global__ void cvt_kernel(CvtArgs a) {
    int m = blockIdx.y;
    int K = a.K[m];
    int i = blockIdx.x * blockDim.x + threadIdx.x;
    if (i < K * 128) {
        int n = i & 127, k = i >> 7;
        g_wtf[a.off[m] + n * K + k] = f2tf(a.src[m][k * 128 + n]);
    }
}

// ---------------- counting sort of edges by col ----------------
__global__ void zero_hist(int n) {
    int i = blockIdx.x * blockDim.x + threadIdx.x;
    if (i < n) g_hist[i] = 0;
}
__global__ void hist_kernel(const int* __restrict__ col, int E) {
    int i = blockIdx.x * blockDim.x + threadIdx.x;
    if (i < E) atomicAdd(&g_hist[col[i]], 1);
}
__global__ void scan1(int n) {
    __shared__ int s[512];
    int i = blockIdx.x * 512 + threadIdx.x;
    s[threadIdx.x] = (i < n) ? g_hist[i] : 0;
    __syncthreads();
    for (int off = 256; off > 0; off >>= 1) {
        if (threadIdx.x < off) s[threadIdx.x] += s[threadIdx.x + off];
        __syncthreads();
    }
    if (threadIdx.x == 0) g_bsum[blockIdx.x] = s[0];
}
__global__ void scan2(int nch) {
    if (threadIdx.x == 0) {
        int run = 0;
        for (int i = 0; i < nch; i++) { int v = g_bsum[i]; g_bsum[i] = run; run += v; }
    }
}
__global__ void scan3(int n) {
    __shared__ int s[512];
    int i = blockIdx.x * 512 + threadIdx.x;
    int v = (i < n) ? g_hist[i] : 0;
    s[threadIdx.x] = v;
    __syncthreads();
    for (int off = 1; off < 512; off <<= 1) {
        int t = (threadIdx.x >= off) ? s[threadIdx.x - off] : 0;
        __syncthreads();
        s[threadIdx.x] += t;
        __syncthreads();
    }
    if (i < n) {
        int excl = s[threadIdx.x] - v + g_bsum[blockIdx.x];
        g_cursor[i] = excl;
        g_deg[i] = (float)v;
    }
}
__global__ void sort_scatter(const int* __restrict__ row, const int* __restrict__ col, int E) {
    int i = blockIdx.x * blockDim.x + threadIdx.x;
    if (i < E) {
        int c = col[i];
        int pos = atomicAdd(&g_cursor[c], 1);
        g_eRowS[pos] = row[i];
        g_eColS[pos] = c;
    }
}

// ---------------- small utility kernels ----------------
__global__ void zero2_kernel(float* p1, int n1, float* p2, int n2) {
    int i = blockIdx.x * blockDim.x + threadIdx.x;
    if (i < n1) p1[i] = 0.0f;
    if (i < n2) p2[i] = 0.0f;
}
__global__ void copy_kernel(const float* __restrict__ s, float* d, int n) {
    int i = blockIdx.x * blockDim.x + threadIdx.x;
    if (i < n) d[i] = s[i];
}

// ---------------- generic node GEMM: out = act(A@W + bias) ----------------
__global__ __launch_bounds__(NT, 2) void gemm_mma(
    const float* __restrict__ A, int K,
    const uint32_t* __restrict__ Wtf,
    const float* __restrict__ bias,
    float* __restrict__ out, int n, int act)
{
    extern __shared__ char smem[];
    uint32_t* sA = (uint32_t*)smem;
    uint32_t sbase = smem_u32(smem);
    int tid = threadIdx.x, wid = tid >> 5, lane = tid & 31;
    int warpM = wid & 3, warpN = wid >> 2;
    int m0 = blockIdx.x * 128;

    if (K == 128) {
        for (int idx = tid; idx < 4096; idx += NT) {
            int m = idx >> 5, q = idx & 31;
            int gm = m0 + m; if (gm >= n) gm = n - 1;
            float4 v = ((const float4*)A)[(size_t)gm * 32 + q];
            uint4 t = {f2tf(v.x), f2tf(v.y), f2tf(v.z), f2tf(v.w)};
            *(uint4*)(sA + m * STRA + q * 4) = t;
        }
    } else {  // K == 64
        for (int idx = tid; idx < 2048; idx += NT) {
            int m = idx >> 4, q = idx & 15;
            int gm = m0 + m; if (gm >= n) gm = n - 1;
            float4 v = ((const float4*)A)[(size_t)gm * 16 + q];
            uint4 t = {f2tf(v.x), f2tf(v.y), f2tf(v.z), f2tf(v.w)};
            *(uint4*)(sA + m * STRA + q * 4) = t;
        }
    }
    float acc[2][8][4];
    acc_zero(acc);
    pipe_gemm(sbase, sbase + SB0_OFF, sbase + SB1_OFF,
              Wtf, K, K >> 5, tid, warpM, warpN, lane, false, acc);

    int l4 = lane >> 2, q2 = (lane & 3) * 2;
#pragma unroll
    for (int mi = 0; mi < 2; mi++)
#pragma unroll
        for (int half = 0; half < 2; half++) {
            int gm = m0 + warpM * 32 + mi * 16 + l4 + half * 8;
            if (gm >= n) continue;
            float* orow = out + (size_t)gm * 128;
#pragma unroll
            for (int ni = 0; ni < 8; ni++) {
                int c = warpN * 64 + ni * 8 + q2;
                float v0 = acc[mi][ni][half * 2 + 0];
                float v1 = acc[mi][ni][half * 2 + 1];
                if (bias) { float2 bv = *(const float2*)(bias + c); v0 += bv.x; v1 += bv.y; }
                if (act)  { v0 = silu(v0); v1 = silu(v1); }
                *(float2*)(orow + c) = make_float2(v0, v1);
            }
        }
}

// ---------------- dual projection (layer 0 only) ----------------
__global__ __launch_bounds__(NT, 2) void proj2(
    const float* __restrict__ A,
    const uint32_t* __restrict__ Wa, const uint32_t* __restrict__ Wb,
    float* __restrict__ outA, float* __restrict__ outB, int n)
{
    extern __shared__ char smem[];
    uint32_t* sA = (uint32_t*)smem;
    uint32_t sbase = smem_u32(smem);
    int tid = threadIdx.x, wid = tid >> 5, lane = tid & 31;
    int warpM = wid & 3, warpN = wid >> 2;
    int m0 = blockIdx.x * 128;

    for (int idx = tid; idx < 4096; idx += NT) {
        int m = idx >> 5, q = idx & 31;
        int gm = m0 + m; if (gm >= n) gm = n - 1;
        float4 v = ((const float4*)A)[(size_t)gm * 32 + q];
        uint4 t = {f2tf(v.x), f2tf(v.y), f2tf(v.z), f2tf(v.w)};
        *(uint4*)(sA + m * STRA + q * 4) = t;
    }
    float acc[2][8][4];
    int l4 = lane >> 2, q2 = (lane & 3) * 2;

    acc_zero(acc);
    pipe_gemm(sbase, sbase + SB0_OFF, sbase + SB1_OFF,
              Wa, 128, 4, tid, warpM, warpN, lane, false, acc);
    prefetch_chunk(sbase + SB0_OFF, Wb, 128, 0, tid);
#pragma unroll
    for (int mi = 0; mi < 2; mi++)
#pragma unroll
        for (int half = 0; half < 2; half++) {
            int gm = m0 + warpM * 32 + mi * 16 + l4 + half * 8;
            if (gm >= n) continue;
            float* orow = outA + (size_t)gm * 128;
#pragma unroll
            for (int ni = 0; ni < 8; ni++) {
                int c = warpN * 64 + ni * 8 + q2;
                *(float2*)(orow + c) = make_float2(acc[mi][ni][half*2+0], acc[mi][ni][half*2+1]);
            }
        }
    acc_zero(acc);
    pipe_gemm(sbase, sbase + SB0_OFF, sbase + SB1_OFF,
              Wb, 128, 4, tid, warpM, warpN, lane, true, acc);
#pragma unroll
    for (int mi = 0; mi < 2; mi++)
#pragma unroll
        for (int half = 0; half < 2; half++) {
            int gm = m0 + warpM * 32 + mi * 16 + l4 + half * 8;
            if (gm >= n) continue;
            float* orow = outB + (size_t)gm * 128;
#pragma unroll
            for (int ni = 0; ni < 8; ni++) {
                int c = warpN * 64 + ni * 8 + q2;
                *(float2*)(orow + c) = make_float2(acc[mi][ni][half*2+0], acc[mi][ni][half*2+1]);
            }
        }
}

// ---- fused node MLP + LN + next-layer projections (+ in-place agg/cup zero, optional eps zero)
__global__ __launch_bounds__(NT, 2) void node_mlp_ln_proj(
    float* __restrict__ agg,
    const uint32_t* __restrict__ Wa, const uint32_t* __restrict__ Wb,
    const float* __restrict__ b1,
    const uint32_t* __restrict__ W2tf, const float* __restrict__ b2,
    const float* __restrict__ lng, const float* __restrict__ lnb,
    float* __restrict__ h, float* __restrict__ x,
    float* __restrict__ cup, const float* __restrict__ deg,
    const uint32_t* __restrict__ WaN, const uint32_t* __restrict__ WbN,
    float* __restrict__ outA, float* __restrict__ outB,
    float* __restrict__ epsZ, int n)
{
    extern __shared__ char smem[];
    uint32_t* sA = (uint32_t*)smem;
    float* sSum = (float*)(smem + SMEM_AB);
    float* sSq  = (float*)(smem + SMEM_AB + 512);
    uint32_t sbase = smem_u32(smem);
    int tid = threadIdx.x, wid = tid >> 5, lane = tid & 31;
    int warpM = wid & 3, warpN = wid >> 2;
    int m0 = blockIdx.x * 128;
    int l4 = lane >> 2, q2 = (lane & 3) * 2;

    if (tid < 128) { sSum[tid] = 0.0f; sSq[tid] = 0.0f; }
    // sA = f2tf(h)
    for (int idx = tid; idx < 4096; idx += NT) {
        int m = idx >> 5, q = idx & 31;
        int gm = m0 + m; if (gm >= n) gm = n - 1;
        float4 v = ((const float4*)h)[(size_t)gm * 32 + q];
        uint4 t = {f2tf(v.x), f2tf(v.y), f2tf(v.z), f2tf(v.w)};
        *(uint4*)(sA + m * STRA + q * 4) = t;
    }
    float acc[2][8][4];
    acc_zero(acc);
    pipe_gemm(sbase, sbase + SB0_OFF, sbase + SB1_OFF,
              Wa, 128, 4, tid, warpM, warpN, lane, false, acc);
    prefetch_chunk(sbase + SB0_OFF, Wb, 128, 0, tid);
    // sA = f2tf(agg); then zero agg in place (own rows only)
    for (int idx = tid; idx < 4096; idx += NT) {
        int m = idx >> 5, q = idx & 31;
        int gm = m0 + m;
        int gmc = (gm >= n) ? n - 1 : gm;
        float4 v = ((const float4*)agg)[(size_t)gmc * 32 + q];
        uint4 t = {f2tf(v.x), f2tf(v.y), f2tf(v.z), f2tf(v.w)};
        *(uint4*)(sA + m * STRA + q * 4) = t;
        if (gm < n) ((float4*)agg)[(size_t)gm * 32 + q] = make_float4(0.f, 0.f, 0.f, 0.f);
    }
    __syncthreads();
    pipe_gemm(sbase, sbase + SB0_OFF, sbase + SB1_OFF,
              Wb, 128, 4, tid, warpM, warpN, lane, true, acc);   // acc = h@Wa + agg@Wb

    prefetch_chunk(sbase + SB0_OFF, W2tf, 128, 0, tid);

    // u = silu(acc + b1) -> sA (tf32)
#pragma unroll
    for (int mi = 0; mi < 2; mi++)
#pragma unroll
        for (int half = 0; half < 2; half++) {
            int rl = warpM * 32 + mi * 16 + l4 + half * 8;
#pragma unroll
            for (int ni = 0; ni < 8; ni++) {
                int c = warpN * 64 + ni * 8 + q2;
                float2 bv = *(const float2*)(b1 + c);
                uint2 t;
                t.x = f2tf(silu(acc[mi][ni][half*2+0] + bv.x));
                t.y = f2tf(silu(acc[mi][ni][half*2+1] + bv.y));
                *(uint2*)(sA + rl * STRA + c) = t;
            }
        }
    __syncthreads();
    acc_zero(acc);
    pipe_gemm(sbase, sbase + SB0_OFF, sbase + SB1_OFF,
              W2tf, 128, 4, tid, warpM, warpN, lane, true, acc);   // acc = u @ W2

    // phase 1: val = h + acc + b2 -> overwrite h (pre-LN); row sums
#pragma unroll
    for (int mi = 0; mi < 2; mi++)
#pragma unroll
        for (int half = 0; half < 2; half++) {
            int rl = warpM * 32 + mi * 16 + l4 + half * 8;
            int gm = m0 + rl;
            float s = 0.0f, s2 = 0.0f;
            if (gm < n) {
                float* hrow = h + (size_t)gm * 128;
#pragma unroll
                for (int ni = 0; ni < 8; ni++) {
                    int c = warpN * 64 + ni * 8 + q2;
                    float2 bv = *(const float2*)(b2 + c);
                    float2 hv = *(const float2*)(hrow + c);
                    float v0 = acc[mi][ni][half*2+0] + bv.x + hv.x;
                    float v1 = acc[mi][ni][half*2+1] + bv.y + hv.y;
                    *(float2*)(hrow + c) = make_float2(v0, v1);
                    s += v0 + v1; s2 += v0*v0 + v1*v1;
                }
            }
            s  += __shfl_xor_sync(0xffffffffu, s, 1);
            s  += __shfl_xor_sync(0xffffffffu, s, 2);
            s2 += __shfl_xor_sync(0xffffffffu, s2, 1);
            s2 += __shfl_xor_sync(0xffffffffu, s2, 2);
            if ((lane & 3) == 0 && gm < n) {
                atomicAdd(&sSum[rl], s);
                atomicAdd(&sSq[rl], s2);
            }
        }
    __syncthreads();
    // phase 2: normalize; write h AND stage tf32(h_new) into sA
    for (int idx = tid; idx < 16384; idx += NT) {
        int rl = idx >> 7, c = idx & 127;
        int gm = m0 + rl;
        float outv = 0.0f;
        if (gm < n) {
            float mu = sSum[rl] * (1.0f / 128.0f);
            float var = sSq[rl] * (1.0f / 128.0f) - mu * mu;
            float val = h[(size_t)gm * 128 + c];
            outv = (val - mu) * rsqrtf(var + 1e-5f) * lng[c] + lnb[c];
            h[(size_t)gm * 128 + c] = outv;
        }
        sA[rl * STRA + c] = f2tf(outv);
    }
    if (tid < 128) {
        int gm = m0 + tid;
        if (gm < n) {
            float inv = __fdividef(1.0f, deg[gm] + 1.0f);
            x[gm*3 + 0] += cup[gm*3 + 0] * inv;
            x[gm*3 + 1] += cup[gm*3 + 1] * inv;
            x[gm*3 + 2] += cup[gm*3 + 2] * inv;
            cup[gm*3 + 0] = 0.0f;
            cup[gm*3 + 1] = 0.0f;
            cup[gm*3 + 2] = 0.0f;
            if (epsZ) {
                epsZ[gm*3 + 0] = 0.0f;
                epsZ[gm*3 + 1] = 0.0f;
                epsZ[gm*3 + 2] = 0.0f;
            }
        }
    }
    // next-layer projections from the staged LN'd tile
    acc_zero(acc);
    pipe_gemm(sbase, sbase + SB0_OFF, sbase + SB1_OFF,
              WaN, 128, 4, tid, warpM, warpN, lane, false, acc);
    prefetch_chunk(sbase + SB0_OFF, WbN, 128, 0, tid);
#pragma unroll
    for (int mi = 0; mi < 2; mi++)
#pragma unroll
        for (int half = 0; half < 2; half++) {
            int gm = m0 + warpM * 32 + mi * 16 + l4 + half * 8;
            if (gm >= n) continue;
            float* orow = outA + (size_t)gm * 128;
#pragma unroll
            for (int ni = 0; ni < 8; ni++) {
                int c = warpN * 64 + ni * 8 + q2;
                *(float2*)(orow + c) = make_float2(acc[mi][ni][half*2+0], acc[mi][ni][half*2+1]);
            }
        }
    acc_zero(acc);
    pipe_gemm(sbase, sbase + SB0_OFF, sbase + SB1_OFF,
              WbN, 128, 4, tid, warpM, warpN, lane, true, acc);
#pragma unroll
    for (int mi = 0; mi < 2; mi++)
#pragma unroll
        for (int half = 0; half < 2; half++) {
            int gm = m0 + warpM * 32 + mi * 16 + l4 + half * 8;
            if (gm >= n) continue;
            float* orow = outB + (size_t)gm * 128;
#pragma unroll
            for (int ni = 0; ni < 8; ni++) {
                int c = warpN * 64 + ni * 8 + q2;
                *(float2*)(orow + c) = make_float2(acc[mi][ni][half*2+0], acc[mi][ni][half*2+1]);
            }
        }
}

// ---------------- fused eps node head: eps += silu(h@W + x@w1x3 + b1) @ W2 + b2 ----------------
__global__ __launch_bounds__(NT, 2) void gemm_eps(
    const float* __restrict__ h,
    const uint32_t* __restrict__ Wtf,
    const float* __restrict__ xin,
    const float* __restrict__ w1x3,
    const float* __restrict__ b1,
    const float* __restrict__ W2,
    const float* __restrict__ b2,
    float* __restrict__ eps, int n)
{
    extern __shared__ char smem[];
    uint32_t* sA = (uint32_t*)smem;
    float* sPart = (float*)(smem + SMEM_AB);   // 384 floats
    uint32_t sbase = smem_u32(smem);
    int tid = threadIdx.x, wid = tid >> 5, lane = tid & 31;
    int warpM = wid & 3, warpN = wid >> 2;
    int m0 = blockIdx.x * 128;
    int l4 = lane >> 2, q2 = (lane & 3) * 2;

    for (int i = tid; i < 384; i += NT) sPart[i] = 0.0f;
    for (int idx = tid; idx < 4096; idx += NT) {
        int m = idx >> 5, q = idx & 31;
        int gm = m0 + m; if (gm >= n) gm = n - 1;
        float4 v = ((const float4*)h)[(size_t)gm * 32 + q];
        uint4 t = {f2tf(v.x), f2tf(v.y), f2tf(v.z), f2tf(v.w)};
        *(uint4*)(sA + m * STRA + q * 4) = t;
    }
    float acc[2][8][4];
    acc_zero(acc);
    pipe_gemm(sbase, sbase + SB0_OFF, sbase + SB1_OFF,
              Wtf, 128, 4, tid, warpM, warpN, lane, false, acc);

    float p0[2][2], p1[2][2], p2[2][2];
#pragma unroll
    for (int mi = 0; mi < 2; mi++)
#pragma unroll
        for (int half = 0; half < 2; half++) {
            p0[mi][half] = 0.0f; p1[mi][half] = 0.0f; p2[mi][half] = 0.0f;
            int gm = m0 + warpM * 32 + mi * 16 + l4 + half * 8;
            if (gm >= n) continue;
            float x0 = xin[gm*3], x1 = xin[gm*3+1], x2 = xin[gm*3+2];
#pragma unroll
            for (int ni = 0; ni < 8; ni++) {
                int c = warpN * 64 + ni * 8 + q2;
#pragma unroll
                for (int j = 0; j < 2; j++) {
                    int cc = c + j;
                    float v = acc[mi][ni][half*2+j]
                            + x0*w1x3[cc] + x1*w1x3[128+cc] + x2*w1x3[256+cc] + b1[cc];
                    float s = silu(v);
                    p0[mi][half] += s * W2[cc*3 + 0];
                    p1[mi][half] += s * W2[cc*3 + 1];
                    p2[mi][half] += s * W2[cc*3 + 2];
                }
            }
        }
#pragma unroll
    for (int mi = 0; mi < 2; mi++)
#pragma unroll
        for (int half = 0; half < 2; half++) {
            p0[mi][half] += __shfl_xor_sync(0xffffffffu, p0[mi][half], 1);
            p0[mi][half] += __shfl_xor_sync(0xffffffffu, p0[mi][half], 2);
            p1[mi][half] += __shfl_xor_sync(0xffffffffu, p1[mi][half], 1);
            p1[mi][half] += __shfl_xor_sync(0xffffffffu, p1[mi][half], 2);
            p2[mi][half] += __shfl_xor_sync(0xffffffffu, p2[mi][half], 1);
            p2[mi][half] += __shfl_xor_sync(0xffffffffu, p2[mi][half], 2);
        }
    if ((lane & 3) == 0) {
#pragma unroll
        for (int mi = 0; mi < 2; mi++)
#pragma unroll
            for (int half = 0; half < 2; half++) {
                int rl = warpM * 32 + mi * 16 + l4 + half * 8;
                atomicAdd(&sPart[rl*3 + 0], p0[mi][half]);
                atomicAdd(&sPart[rl*3 + 1], p1[mi][half]);
                atomicAdd(&sPart[rl*3 + 2], p2[mi][half]);
            }
    }
    __syncthreads();
    if (tid < 128) {
        int gm = m0 + tid;
        if (gm < n) {
            eps[gm*3 + 0] += sPart[tid*3 + 0] + b2[0];
            eps[gm*3 + 1] += sPart[tid*3 + 1] + b2[1];
            eps[gm*3 + 2] += sPart[tid*3 + 2] + b2[2];
        }
    }
}

// ---------------- edge aux layout ----------------
#define AUX_ROW   0
#define AUX_COL   512
#define AUX_VAL   1024
#define AUX_DIST  1536
#define AUX_RELX  2048
#define AUX_RELY  2560
#define AUX_RELZ  3072
#define AUX_PART  3584
#define AUX_SEG   5120
#define AUX_NSEG  5648
#define AUX_WTOT  5652
#define AUX_SIZE  5696

__device__ __forceinline__ void build_segments(char* aux, int tid, int wid, int lane) {
    int* sCol = (int*)(aux + AUX_COL);
    int* sSeg = (int*)(aux + AUX_SEG);
    int* sNseg = (int*)(aux + AUX_NSEG);
    int* sW = (int*)(aux + AUX_WTOT);
    int flag = 0, pre = 0;
    if (tid < 128) {
        flag = (tid == 0) || (sCol[tid] != sCol[tid - 1]);
        unsigned bm = __ballot_sync(0xffffffffu, flag);
        pre = __popc(bm & ((1u << lane) - 1));
        if (lane == 0) sW[wid] = __popc(bm);
    }
    __syncthreads();
    if (tid < 128 && flag) {
        int off = 0;
        for (int w = 0; w < wid; w++) off += sW[w];
        sSeg[off + pre] = tid;
    }
    if (tid == 0) {
        int t = sW[0] + sW[1] + sW[2] + sW[3];
        sNseg[0] = t;
        sSeg[t] = 128;
    }
    __syncthreads();
}

// ---------------- fused edge kernel (message-passing layer) ----------------
__global__ __launch_bounds__(NT, 2) void edge_layer_mma(
    const int* __restrict__ eRow, const int* __restrict__ eCol, int E,
    const float* __restrict__ x,
    const float* __restrict__ hA, const float* __restrict__ hB,
    const float* __restrict__ w1c, const float* __restrict__ b1,
    const uint32_t* __restrict__ W2tf, const float* __restrict__ b2,
    const uint32_t* __restrict__ Cw1tf, const float* __restrict__ cb1,
    const float* __restrict__ cw2,
    float* __restrict__ agg, float* __restrict__ cupd)
{
    extern __shared__ char smem[];
    uint32_t* sA = (uint32_t*)smem;
    char* aux = smem + SMEM_AB;
    int*   sRow   = (int*)(aux + AUX_ROW);
    int*   sCol   = (int*)(aux + AUX_COL);
    int*   sValid = (int*)(aux + AUX_VAL);
    float* sDist  = (float*)(aux + AUX_DIST);
    float* sRelx  = (float*)(aux + AUX_RELX);
    float* sRely  = (float*)(aux + AUX_RELY);
    float* sRelz  = (float*)(aux + AUX_RELZ);
    float* sPart  = (float*)(aux + AUX_PART);
    int*   sSeg   = (int*)(aux + AUX_SEG);
    int*   sNseg  = (int*)(aux + AUX_NSEG);
    uint32_t sbase = smem_u32(smem);

    int tid = threadIdx.x, wid = tid >> 5, lane = tid & 31;
    int warpM = wid & 3, warpN = wid >> 2;
    int e0 = blockIdx.x * 128;

    prefetch_chunk(sbase + SB0_OFF, W2tf, 128, 0, tid);

    if (tid < 128) {
        sPart[tid] = 0.0f;
        int e = e0 + tid;
        int valid = (e < E); if (!valid) e = E - 1;
        int r = eRow[e], c = eCol[e];
        float rx = x[r*3]   - x[c*3];
        float ry = x[r*3+1] - x[c*3+1];
        float rz = x[r*3+2] - x[c*3+2];
        float d = sqrtf(rx*rx + ry*ry + rz*rz);
        sRow[tid] = r; sCol[tid] = c; sValid[tid] = valid;
        sDist[tid] = d; sRelx[tid] = rx; sRely[tid] = ry; sRelz[tid] = rz;
    }
    __syncthreads();
    build_segments(aux, tid, wid, lane);

    {   // sA[e][k] = silu(t1), two threads per edge
        int e = tid >> 1, j0 = (tid & 1) * 64;
        int r = sRow[e], c = sCol[e];
        float d = sDist[e];
        const float4* pa  = (const float4*)(hA  + (size_t)r * 128 + j0);
        const float4* pb  = (const float4*)(hB  + (size_t)c * 128 + j0);
        const float4* pw  = (const float4*)(w1c + j0);
        const float4* pb1 = (const float4*)(b1  + j0);
        uint32_t* dst = sA + e * STRA + j0;
#pragma unroll
        for (int q = 0; q < 16; q++) {
            float4 a = pa[q], b = pb[q], w = pw[q], bb = pb1[q];
            uint4 v;
            v.x = f2tf(silu(a.x + b.x + d * w.x + bb.x));
            v.y = f2tf(silu(a.y + b.y + d * w.y + bb.y));
            v.z = f2tf(silu(a.z + b.z + d * w.z + bb.z));
            v.w = f2tf(silu(a.w + b.w + d * w.w + bb.w));
            *(uint4*)(dst + q * 4) = v;
        }
    }
    __syncthreads();

    float acc[2][8][4];
    acc_zero(acc);
    pipe_gemm(sbase, sbase + SB0_OFF, sbase + SB1_OFF,
              W2tf, 128, 4, tid, warpM, warpN, lane, true, acc);   // D1 = U @ m_w2

    prefetch_chunk(sbase + SB0_OFF, Cw1tf, 128, 0, tid);

    int l4 = lane >> 2, q2 = (lane & 3) * 2;
    {   // msg = silu(D1 + b2) into sA (zero invalid rows)
        float2 bv[8];
#pragma unroll
        for (int ni = 0; ni < 8; ni++) bv[ni] = *(const float2*)(b2 + warpN * 64 + ni * 8 + q2);
#pragma unroll
        for (int mi = 0; mi < 2; mi++)
#pragma unroll
            for (int half = 0; half < 2; half++) {
                int e = warpM * 32 + mi * 16 + l4 + half * 8;
                float vscale = sValid[e] ? 1.0f : 0.0f;
#pragma unroll
                for (int ni = 0; ni < 8; ni++) {
                    int c = warpN * 64 + ni * 8 + q2;
                    float m0 = silu(acc[mi][ni][half*2+0] + bv[ni].x) * vscale;
                    float m1 = silu(acc[mi][ni][half*2+1] + bv[ni].y) * vscale;
                    uint2 t; t.x = f2tf(m0); t.y = f2tf(m1);
                    *(uint2*)(sA + e * STRA + c) = t;
                }
            }
    }
    __syncthreads();
    acc_zero(acc);
    pipe_gemm(sbase, sbase + SB0_OFF, sbase + SB1_OFF,
              Cw1tf, 128, 4, tid, warpM, warpN, lane, true, acc);   // D2 = msg @ c_w1

    float2 cbv[8], cwv[8];
#pragma unroll
    for (int ni = 0; ni < 8; ni++) {
        int c = warpN * 64 + ni * 8 + q2;
        cbv[ni] = *(const float2*)(cb1 + c);
        cwv[ni] = *(const float2*)(cw2 + c);
    }
    float p[2][2];
    p[0][0] = p[0][1] = p[1][0] = p[1][1] = 0.0f;
#pragma unroll
    for (int ni = 0; ni < 8; ni++)
#pragma unroll
        for (int mi = 0; mi < 2; mi++)
#pragma unroll
            for (int half = 0; half < 2; half++)
                p[mi][half] += silu(acc[mi][ni][half*2+0] + cbv[ni].x) * cwv[ni].x
                             + silu(acc[mi][ni][half*2+1] + cbv[ni].y) * cwv[ni].y;
#pragma unroll
    for (int mi = 0; mi < 2; mi++)
#pragma unroll
        for (int half = 0; half < 2; half++) {
            p[mi][half] += __shfl_xor_sync(0xffffffffu, p[mi][half], 1);
            p[mi][half] += __shfl_xor_sync(0xffffffffu, p[mi][half], 2);
        }
    if ((lane & 3) == 0) {
#pragma unroll
        for (int mi = 0; mi < 2; mi++)
#pragma unroll
            for (int half = 0; half < 2; half++)
                atomicAdd(&sPart[warpM * 32 + mi * 16 + l4 + half * 8], p[mi][half]);
    }
    __syncthreads();

    int nseg = sNseg[0];
    {   // segmented agg reduction
        int c = tid & 127, grp = tid >> 7;
        for (int s = grp; s < nseg; s += 2) {
            int st = sSeg[s], en = sSeg[s + 1];
            float a = 0.0f;
            for (int e = st; e < en; e++) a += __uint_as_float(sA[e * STRA + c]);
            red1(agg + (size_t)sCol[st] * 128 + c, a);
        }
    }
    if (tid < nseg) {
        int st = sSeg[tid], en = sSeg[tid + 1];
        float ax = 0, ay = 0, az = 0;
        for (int e = st; e < en; e++) {
            if (!sValid[e]) continue;
            float cm = tanh_ap(sPart[e]);
            float f = __fdividef(cm, sDist[e] + 1e-8f);
            ax += f * sRelx[e]; ay += f * sRely[e]; az += f * sRelz[e];
        }
        int cN = sCol[st];
        red1(cupd + cN*3 + 0, ax);
        red1(cupd + cN*3 + 1, ay);
        red1(cupd + cN*3 + 2, az);
    }
}

// ---------------- fused edge kernel (epsilon head) ----------------
__global__ __launch_bounds__(NT, 2) void edge_eps_mma(
    const int* __restrict__ eRow, const int* __restrict__ eCol, int E,
    const float* __restrict__ x,
    const float* __restrict__ hA, const float* __restrict__ hB,
    const float* __restrict__ wRel, const float* __restrict__ b1,
    const uint32_t* __restrict__ W2tf, const float* __restrict__ b2,
    const uint32_t* __restrict__ Cw1tf, const float* __restrict__ cb1,
    const float* __restrict__ cw2, const float* __restrict__ cb2,
    float* __restrict__ eps)
{
    extern __shared__ char smem[];
    uint32_t* sA = (uint32_t*)smem;
    char* aux = smem + SMEM_AB;
    int*   sRow   = (int*)(aux + AUX_ROW);
    int*   sCol   = (int*)(aux + AUX_COL);
    int*   sValid = (int*)(aux + AUX_VAL);
    float* sDist  = (float*)(aux + AUX_DIST);
    float* sRelx  = (float*)(aux + AUX_RELX);
    float* sRely  = (float*)(aux + AUX_RELY);
    float* sRelz  = (float*)(aux + AUX_RELZ);
    float* sPart  = (float*)(aux + AUX_PART);
    int*   sSeg   = (int*)(aux + AUX_SEG);
    int*   sNseg  = (int*)(aux + AUX_NSEG);
    uint32_t sbase = smem_u32(smem);

    int tid = threadIdx.x, wid = tid >> 5, lane = tid & 31;
    int warpM = wid & 3, warpN = wid >> 2;
    int e0 = blockIdx.x * 128;

    prefetch_chunk(sbase + SB0_OFF, W2tf, 128, 0, tid);

    for (int i = tid; i < 384; i += NT) sPart[i] = 0.0f;
    if (tid < 128) {
        int e = e0 + tid;
        int valid = (e < E); if (!valid) e = E - 1;
        int r = eRow[e], c = eCol[e];
        float rx = x[r*3]   - x[c*3];
        float ry = x[r*3+1] - x[c*3+1];
        float rz = x[r*3+2] - x[c*3+2];
        float d = sqrtf(rx*rx + ry*ry + rz*rz);
        sRow[tid] = r; sCol[tid] = c; sValid[tid] = valid;
        sDist[tid] = d; sRelx[tid] = rx; sRely[tid] = ry; sRelz[tid] = rz;
    }
    __syncthreads();
    build_segments(aux, tid, wid, lane);

    {
        int e = tid >> 1, j0 = (tid & 1) * 64;
        int r = sRow[e], c = sCol[e];
        float d = sDist[e], rx = sRelx[e], ry = sRely[e], rz = sRelz[e];
        const float4* pa  = (const float4*)(hA + (size_t)r * 128 + j0);
        const float4* pb  = (const float4*)(hB + (size_t)c * 128 + j0);
        const float4* pwx = (const float4*)(wRel + j0);
        const float4* pwy = (const float4*)(wRel + 128 + j0);
        const float4* pwz = (const float4*)(wRel + 256 + j0);
        const float4* pwd = (const float4*)(wRel + 384 + j0);
        const float4* pb1 = (const float4*)(b1 + j0);
        uint32_t* dst = sA + e * STRA + j0;
#pragma unroll
        for (int q = 0; q < 16; q++) {
            float4 a = pa[q], b = pb[q];
            float4 wx = pwx[q], wy = pwy[q], wz = pwz[q], wd = pwd[q], bb = pb1[q];
            uint4 v;
            v.x = f2tf(silu(a.x + b.x + rx*wx.x + ry*wy.x + rz*wz.x + d*wd.x + bb.x));
            v.y = f2tf(silu(a.y + b.y + rx*wx.y + ry*wy.y + rz*wz.y + d*wd.y + bb.y));
            v.z = f2tf(silu(a.z + b.z + rx*wx.z + ry*wy.z + rz*wz.z + d*wd.z + bb.z));
            v.w = f2tf(silu(a.w + b.w + rx*wx.w + ry*wy.w + rz*wz.w + d*wd.w + bb.w));
            *(uint4*)(dst + q * 4) = v;
        }
    }
    __syncthreads();

    float acc[2][8][4];
    acc_zero(acc);
    pipe_gemm(sbase, sbase + SB0_OFF, sbase + SB1_OFF,
              W2tf, 128, 4, tid, warpM, warpN, lane, true, acc);

    prefetch_chunk(sbase + SB0_OFF, Cw1tf, 128, 0, tid);

    int l4 = lane >> 2, q2 = (lane & 3) * 2;
    {
        float2 bv[8];
#pragma unroll
        for (int ni = 0; ni < 8; ni++) bv[ni] = *(const float2*)(b2 + warpN * 64 + ni * 8 + q2);
#pragma unroll
        for (int mi = 0; mi < 2; mi++)
#pragma unroll
            for (int half = 0; half < 2; half++) {
                int e = warpM * 32 + mi * 16 + l4 + half * 8;
#pragma unroll
                for (int ni = 0; ni < 8; ni++) {
                    int c = warpN * 64 + ni * 8 + q2;
                    uint2 t;
                    t.x = f2tf(silu(acc[mi][ni][half*2+0] + bv[ni].x));
                    t.y = f2tf(silu(acc[mi][ni][half*2+1] + bv[ni].y));
                    *(uint2*)(sA + e * STRA + c) = t;
                }
            }
    }
    __syncthreads();
    acc_zero(acc);
    pipe_gemm(sbase, sbase + SB0_OFF, sbase + SB1_OFF,
              Cw1tf, 128, 4, tid, warpM, warpN, lane, true, acc);

    float p0[2][2], p1[2][2], p2[2][2];
#pragma unroll
    for (int mi = 0; mi < 2; mi++)
#pragma unroll
        for (int half = 0; half < 2; half++) {
            p0[mi][half] = 0.0f; p1[mi][half] = 0.0f; p2[mi][half] = 0.0f;
        }
#pragma unroll
    for (int ni = 0; ni < 8; ni++) {
        int c = warpN * 64 + ni * 8 + q2;
        float2 cbv = *(const float2*)(cb1 + c);
        float w00 = cw2[c*3+0], w01 = cw2[c*3+1], w02 = cw2[c*3+2];
        float w10 = cw2[c*3+3], w11 = cw2[c*3+4], w12 = cw2[c*3+5];
#pragma unroll
        for (int mi = 0; mi < 2; mi++)
#pragma unroll
            for (int half = 0; half < 2; half++) {
                float v0 = silu(acc[mi][ni][half*2+0] + cbv.x);
                float v1 = silu(acc[mi][ni][half*2+1] + cbv.y);
                p0[mi][half] += v0*w00 + v1*w10;
                p1[mi][half] += v0*w01 + v1*w11;
                p2[mi][half] += v0*w02 + v1*w12;
            }
    }
#pragma unroll
    for (int mi = 0; mi < 2; mi++)
#pragma unroll
        for (int half = 0; half < 2; half++) {
            p0[mi][half] += __shfl_xor_sync(0xffffffffu, p0[mi][half], 1);
            p0[mi][half] += __shfl_xor_sync(0xffffffffu, p0[mi][half], 2);
            p1[mi][half] += __shfl_xor_sync(0xffffffffu, p1[mi][half], 1);
            p1[mi][half] += __shfl_xor_sync(0xffffffffu, p1[mi][half], 2);
            p2[mi][half] += __shfl_xor_sync(0xffffffffu, p2[mi][half], 1);
            p2[mi][half] += __shfl_xor_sync(0xffffffffu, p2[mi][half], 2);
        }
    if ((lane & 3) == 0) {
#pragma unroll
        for (int mi = 0; mi < 2; mi++)
#pragma unroll
            for (int half = 0; half < 2; half++) {
                int e = warpM * 32 + mi * 16 + l4 + half * 8;
                atomicAdd(&sPart[e*3 + 0], p0[mi][half]);
                atomicAdd(&sPart[e*3 + 1], p1[mi][half]);
                atomicAdd(&sPart[e*3 + 2], p2[mi][half]);
            }
    }
    __syncthreads();

    int nseg = sNseg[0];
    if (tid < nseg) {
        int st = sSeg[tid], en = sSeg[tid + 1];
        float a0 = 0, a1 = 0, a2 = 0; int cnt = 0;
        for (int e = st; e < en; e++) {
            if (!sValid[e]) continue;
            a0 += sPart[e*3 + 0]; a1 += sPart[e*3 + 1]; a2 += sPart[e*3 + 2];
            cnt++;
        }
        int cN = sCol[st];
        red1(eps + cN*3 + 0, a0 + cnt * cb2[0]);
        red1(eps + cN*3 + 1, a1 + cnt * cb2[1]);
        red1(eps + cN*3 + 2, a2 + cnt * cb2[2]);
    }
}

// ---------------- pack output: [h | x | eps] ----------------
__global__ void pack_kernel(const float* __restrict__ h, const float* __restrict__ x,
                            const float* __restrict__ eps, float* __restrict__ out, int n)
{
    int i = blockIdx.x * blockDim.x + threadIdx.x;
    int nh = n * 128;
    if (i < nh) out[i] = h[i];
    else if (i < nh + 3*n) out[i] = x[i - nh];
    else if (i < nh + 6*n) out[i] = eps[i - nh - 3*n];
}

// ---------------- host ----------------
static const int NODE_SMEM = SMEM_AB;
static const int LN_SMEM   = SMEM_AB + 1024;
static const int EPS_SMEM  = SMEM_AB + 1536;
static const int EDGE_SMEM = SMEM_AB + AUX_SIZE;

#define OFF_MW1A 0
#define OFF_MW1B 65536
#define OFF_MW2  131072
#define OFF_CW1  196608
#define OFF_NW1A 262144
#define OFF_NW1B 327680
#define OFF_NW2  393216
#define OFF_EMW1A 458752
#define OFF_EMW1B 475136
#define OFF_EMW2 491520
#define OFF_ECW1 507904
#define OFF_EHW1 524288
#define OFF_EMB  540672

extern "C" void kernel_launch(void* const* d_in, const int* in_sizes, int n_in,
                              void* d_out, int out_size)
{
    const float* in_h  = (const float*)d_in[0];
    const float* in_x  = (const float*)d_in[1];
    const int*   eidx  = (const int*)d_in[2];
    const float* emb_w = (const float*)d_in[3];
    const float* emb_b = (const float*)d_in[4];
    const float* m_w1  = (const float*)d_in[5];
    const float* m_b1  = (const float*)d_in[6];
    const float* m_w2  = (const float*)d_in[7];
    const float* m_b2  = (const float*)d_in[8];
    const float* c_w1  = (const float*)d_in[9];
    const float* c_b1  = (const float*)d_in[10];
    const float* c_w2  = (const float*)d_in[11];
    const float* n_w1  = (const float*)d_in[12];
    const float* n_b1  = (const float*)d_in[13];
    const float* n_w2  = (const float*)d_in[14];
    const float* n_b2  = (const float*)d_in[15];
    const float* ln_g  = (const float*)d_in[16];
    const float* ln_b  = (const float*)d_in[17];
    const float* em_w1 = (const float*)d_in[18];
    const float* em_b1 = (const float*)d_in[19];
    const float* em_w2 = (const float*)d_in[20];
    const float* em_b2 = (const float*)d_in[21];
    const float* ec_w1 = (const float*)d_in[22];
    const float* ec_b1 = (const float*)d_in[23];
    const float* ec_w2 = (const float*)d_in[24];
    const float* ec_b2 = (const float*)d_in[25];
    const float* eh_w1 = (const float*)d_in[26];
    const float* eh_b1 = (const float*)d_in[27];
    const float* eh_w2 = (const float*)d_in[28];
    const float* eh_b2 = (const float*)d_in[29];

    int n = in_sizes[0] / 64;
    int E = in_sizes[2] / 2;
    const int* eRow = eidx;
    const int* eCol = eidx + E;

    float *h, *x, *hA, *hB, *agg, *cup, *eps, *deg;
    uint32_t* wtf;
    int *eRowS, *eColS;
    cudaGetSymbolAddress((void**)&h,   g_h);
    cudaGetSymbolAddress((void**)&x,   g_x);
    cudaGetSymbolAddress((void**)&hA,  g_hA);
    cudaGetSymbolAddress((void**)&hB,  g_hB);
    cudaGetSymbolAddress((void**)&agg, g_agg);
    cudaGetSymbolAddress((void**)&cup, g_cup);
    cudaGetSymbolAddress((void**)&eps, g_eps);
    cudaGetSymbolAddress((void**)&deg, g_deg);
    cudaGetSymbolAddress((void**)&wtf, g_wtf);
    cudaGetSymbolAddress((void**)&eRowS, g_eRowS);
    cudaGetSymbolAddress((void**)&eColS, g_eColS);

    cudaFuncSetAttribute(gemm_mma,         cudaFuncAttributeMaxDynamicSharedMemorySize, NODE_SMEM);
    cudaFuncSetAttribute(proj2,            cudaFuncAttributeMaxDynamicSharedMemorySize, NODE_SMEM);
    cudaFuncSetAttribute(node_mlp_ln_proj, cudaFuncAttributeMaxDynamicSharedMemorySize, LN_SMEM);
    cudaFuncSetAttribute(gemm_eps,         cudaFuncAttributeMaxDynamicSharedMemorySize, EPS_SMEM);
    cudaFuncSetAttribute(edge_layer_mma,   cudaFuncAttributeMaxDynamicSharedMemorySize, EDGE_SMEM);
    cudaFuncSetAttribute(edge_eps_mma,     cudaFuncAttributeMaxDynamicSharedMemorySize, EDGE_SMEM);

    // weights -> tf32 n-major
    {
        CvtArgs a;
        int idx = 0;
        for (int i = 0; i < 4; i++) { a.src[idx] = m_w1 + (size_t)i*32896;          a.off[idx] = OFF_MW1A + i*16384; a.K[idx] = 128; idx++; }
        for (int i = 0; i < 4; i++) { a.src[idx] = m_w1 + (size_t)i*32896 + 16384;  a.off[idx] = OFF_MW1B + i*16384; a.K[idx] = 128; idx++; }
        for (int i = 0; i < 4; i++) { a.src[idx] = m_w2 + (size_t)i*16384;          a.off[idx] = OFF_MW2 + i*16384;  a.K[idx] = 128; idx++; }
        for (int i = 0; i < 4; i++) { a.src[idx] = c_w1 + (size_t)i*16384;          a.off[idx] = OFF_CW1 + i*16384;  a.K[idx] = 128; idx++; }
        for (int i = 0; i < 4; i++) { a.src[idx] = n_w1 + (size_t)i*32768;          a.off[idx] = OFF_NW1A + i*16384; a.K[idx] = 128; idx++; }
        for (int i = 0; i < 4; i++) { a.src[idx] = n_w1 + (size_t)i*32768 + 16384;  a.off[idx] = OFF_NW1B + i*16384; a.K[idx] = 128; idx++; }
        for (int i = 0; i < 4; i++) { a.src[idx] = n_w2 + (size_t)i*16384;          a.off[idx] = OFF_NW2 + i*16384;  a.K[idx] = 128; idx++; }
        a.src[idx] = em_w1;          a.off[idx] = OFF_EMW1A; a.K[idx] = 128; idx++;
        a.src[idx] = em_w1 + 16384;  a.off[idx] = OFF_EMW1B; a.K[idx] = 128; idx++;
        a.src[idx] = em_w2;          a.off[idx] = OFF_EMW2;  a.K[idx] = 128; idx++;
        a.src[idx] = ec_w1;          a.off[idx] = OFF_ECW1;  a.K[idx] = 128; idx++;
        a.src[idx] = eh_w1;          a.off[idx] = OFF_EHW1;  a.K[idx] = 128; idx++;
        a.src[idx] = emb_w;          a.off[idx] = OFF_EMB;   a.K[idx] = 64;  idx++;
        dim3 g(64, 34);
        cvt_kernel<<<g, 256>>>(a);
    }

    // counting sort of edges by col (also produces deg)
    int nch = (n + 511) / 512;
    zero_hist<<<(n + 255)/256, 256>>>(n);
    hist_kernel<<<(E + 255)/256, 256>>>(eCol, E);
    scan1<<<nch, 512>>>(n);
    scan2<<<1, 32>>>(nch);
    scan3<<<nch, 512>>>(n);
    sort_scatter<<<(E + 255)/256, 256>>>(eRow, eCol, E);

    int gN = (n + 127) / 128;
    int gE = (E + 127) / 128;

    gemm_mma<<<gN, NT, NODE_SMEM>>>(in_h, 64, wtf + OFF_EMB, emb_b, h, n, 0);
    copy_kernel<<<(3*n + 255)/256, 256>>>(in_x, x, 3*n);
    proj2<<<gN, NT, NODE_SMEM>>>(h, wtf + OFF_MW1A, wtf + OFF_MW1B, hA, hB, n);
    zero2_kernel<<<(n*128 + 255)/256, 256>>>(agg, n*128, cup, 3*n);   // layer 0 init only

    for (int i = 0; i < 4; i++) {
        edge_layer_mma<<<gE, NT, EDGE_SMEM>>>(
            eRowS, eColS, E, x, hA, hB,
            m_w1 + (size_t)i*32896 + 32768, m_b1 + i*128,
            wtf + OFF_MW2 + i*16384, m_b2 + i*128,
            wtf + OFF_CW1 + i*16384, c_b1 + i*128, c_w2 + i*128,
            agg, cup);
        const uint32_t* WaN = (i < 3) ? (wtf + OFF_MW1A + (i+1)*16384) : (wtf + OFF_EMW1A);
        const uint32_t* WbN = (i < 3) ? (wtf + OFF_MW1B + (i+1)*16384) : (wtf + OFF_EMW1B);
        float* epsZ = (i == 3) ? eps : nullptr;   // zero eps just before edge_eps
        node_mlp_ln_proj<<<gN, NT, LN_SMEM>>>(agg,
            wtf + OFF_NW1A + i*16384, wtf + OFF_NW1B + i*16384, n_b1 + i*128,
            wtf + OFF_NW2 + i*16384, n_b2 + i*128,
            ln_g + i*128, ln_b + i*128, h, x, cup, deg,
            WaN, WbN, hA, hB, epsZ, n);
    }

    edge_eps_mma<<<gE, NT, EDGE_SMEM>>>(
        eRowS, eColS, E, x, hA, hB,
        em_w1 + 32768, em_b1,
        wtf + OFF_EMW2, em_b2, wtf + OFF_ECW1, ec_b1, ec_w2, ec_b2, eps);
    gemm_eps<<<gN, NT, EPS_SMEM>>>(h, wtf + OFF_EHW1, x,
        eh_w1 + 128*128, eh_b1, eh_w2, eh_b2, eps, n);

    pack_kernel<<<(n*134 + 255)/256, 256>>>(h, x, eps, (float*)d_out, n);
}

// round 16
// speedup vs baseline: 1.1356x; 1.1356x over previous
#include <cuda_runtime.h>
#include <math.h>
#include <stdint.h>

#define MAXN 50048
#define MAXE 800256
typedef unsigned long long u64;

// ---------------- scratch (static device arrays; no cudaMalloc) ----------------
__device__ float g_h  [MAXN*128];
__device__ float g_x  [MAXN*3];
__device__ float g_hA [MAXN*128];
__device__ float g_hB [MAXN*128];
__device__ float g_agg[MAXN*128];
__device__ float g_cup[MAXN*3];
__device__ float g_eps[MAXN*3];
__device__ float g_deg[MAXN];
__device__ uint32_t g_wtf[550272];   // weights tf32, n-major [n][K]
__device__ int g_hist[MAXN];
__device__ int g_bsum[256];
__device__ int g_cursor[MAXN];
__device__ int g_eRowS[MAXE];
__device__ int g_eColS[MAXE];

// ---------------- helpers ----------------
__device__ __forceinline__ float tanh_ap(float x) {
    float t; asm("tanh.approx.f32 %0,%1;" : "=f"(t) : "f"(x)); return t;
}
__device__ __forceinline__ float silu(float x) {
    return 0.5f * x * (1.0f + tanh_ap(0.5f * x));
}
__device__ __forceinline__ uint32_t f2tf(float f) {
    uint32_t r; asm("cvt.rna.tf32.f32 %0, %1;" : "=r"(r) : "f"(f)); return r;
}
__device__ __forceinline__ uint32_t smem_u32(const void* p) {
    uint32_t a;
    asm("{ .reg .u64 t; cvta.to.shared.u64 t, %1; cvt.u32.u64 %0, t; }" : "=r"(a) : "l"(p));
    return a;
}
__device__ __forceinline__ void mma8(float d[4], uint32_t a0, uint32_t a1, uint32_t a2, uint32_t a3,
                                     uint32_t b0, uint32_t b1) {
    asm volatile(
        "mma.sync.aligned.m16n8k8.row.col.f32.tf32.tf32.f32 "
        "{%0,%1,%2,%3},{%4,%5,%6,%7},{%8,%9},{%0,%1,%2,%3};"
        : "+f"(d[0]), "+f"(d[1]), "+f"(d[2]), "+f"(d[3])
        : "r"(a0), "r"(a1), "r"(a2), "r"(a3), "r"(b0), "r"(b1));
}
__device__ __forceinline__ void ldsm4(uint32_t& r0, uint32_t& r1, uint32_t& r2, uint32_t& r3, uint32_t addr) {
    asm volatile("ldmatrix.sync.aligned.m8n8.x4.shared.b16 {%0,%1,%2,%3},[%4];"
        : "=r"(r0), "=r"(r1), "=r"(r2), "=r"(r3) : "r"(addr));
}
__device__ __forceinline__ void red1(float* p, float a) {
    asm volatile("red.global.add.f32 [%0],%1;" :: "l"(p), "f"(a) : "memory");
}
__device__ __forceinline__ void cpa16(uint32_t saddr, const void* g) {
    asm volatile("cp.async.ca.shared.global [%0], [%1], 16;" :: "r"(saddr), "l"(g));
}
#define CP_COMMIT() asm volatile("cp.async.commit_group;" ::: "memory")
#define CP_WAIT1()  asm volatile("cp.async.wait_group 1;" ::: "memory")
#define CP_WAIT0()  asm volatile("cp.async.wait_group 0;" ::: "memory")

#define NT 256
#define STRA 132
#define STRB 36
#define SA_BYTES (128*STRA*4)           // 67584
#define CHUNK_BYTES (128*STRB*4)        // 18432
#define SB0_OFF SA_BYTES
#define SB1_OFF (SA_BYTES + CHUNK_BYTES)
#define SMEM_AB (SA_BYTES + 2*CHUNK_BYTES)   // 104448

__device__ __forceinline__ void prefetch_chunk(uint32_t dstAddr, const uint32_t* __restrict__ src,
                                               int Ksrc, int c, int tid) {
#pragma unroll
    for (int i = 0; i < 4; i++) {
        int u = tid + i * NT;
        int nn = u >> 3, kq = u & 7;
        cpa16(dstAddr + (uint32_t)(nn * STRB + kq * 4) * 4, src + nn * Ksrc + c * 32 + kq * 4);
    }
    CP_COMMIT();
}

__device__ __forceinline__ void mma_chunk(uint32_t sAaddr, uint32_t sBaddr,
                                          int warpM, int warpN, int lane, int kbase,
                                          float acc[2][8][4]) {
    uint32_t aBase = sAaddr + (uint32_t)((warpM*32 + (lane & 7) + ((lane >> 3) & 1) * 8) * STRA
                                         + (lane >> 4) * 4 + kbase) * 4;
    uint32_t bBase = sBaddr + (uint32_t)((warpN*64 + (lane >> 3) * 8 + (lane & 7)) * STRB) * 4;
#pragma unroll
    for (int kk = 0; kk < 32; kk += 8) {
        uint32_t a[2][4], b[2][2][4];
#pragma unroll
        for (int mi = 0; mi < 2; mi++)
            ldsm4(a[mi][0], a[mi][1], a[mi][2], a[mi][3], aBase + (uint32_t)(mi * 16 * STRA + kk) * 4);
#pragma unroll
        for (int nh = 0; nh < 2; nh++)
#pragma unroll
            for (int kh = 0; kh < 2; kh++)
                ldsm4(b[nh][kh][0], b[nh][kh][1], b[nh][kh][2], b[nh][kh][3],
                      bBase + (uint32_t)(nh * 32 * STRB + kk + kh * 4) * 4);
#pragma unroll
        for (int mi = 0; mi < 2; mi++)
#pragma unroll
            for (int nh = 0; nh < 2; nh++)
#pragma unroll
                for (int j = 0; j < 4; j++)
                    mma8(acc[mi][nh * 4 + j], a[mi][0], a[mi][1], a[mi][2], a[mi][3],
                         b[nh][0][j], b[nh][1][j]);
    }
}
__device__ __forceinline__ void acc_zero(float acc[2][8][4]) {
#pragma unroll
    for (int mi = 0; mi < 2; mi++)
#pragma unroll
        for (int ni = 0; ni < 8; ni++)
#pragma unroll
            for (int j = 0; j < 4; j++) acc[mi][ni][j] = 0.0f;
}
__device__ __forceinline__ void pipe_gemm(uint32_t sAaddr, uint32_t sb0a, uint32_t sb1a,
    const uint32_t* __restrict__ W, int Ksrc, int nchunks, int tid,
    int warpM, int warpN, int lane, bool c0done, float acc[2][8][4])
{
    if (!c0done) prefetch_chunk(sb0a, W, Ksrc, 0, tid);
    for (int c = 0; c < nchunks; c++) {
        if (c + 1 < nchunks) {
            prefetch_chunk((c & 1) ? sb0a : sb1a, W, Ksrc, c + 1, tid);
            CP_WAIT1();
        } else {
            CP_WAIT0();
        }
        __syncthreads();
        mma_chunk(sAaddr, (c & 1) ? sb1a : sb0a, warpM, warpN, lane, c * 32, acc);
        __syncthreads();
    }
}

// ---------------- weight pre-conversion (transpose to n-major tf32) ----------------
struct CvtArgs { const float* src[34]; int off[34]; int K[34]; };
__global__ void cvt_kernel(CvtArgs a) {
    int m = blockIdx.y;
    int K = a.K[m];
    int i = blockIdx.x * blockDim.x + threadIdx.x;
    if (i < K * 128) {
        int n = i & 127, k = i >> 7;
        g_wtf[a.off[m] + n * K + k] = f2tf(a.src[m][k * 128 + n]);
    }
}

// ---------------- counting sort of edges by col ----------------
__global__ void zero_hist(int n) {
    int i = blockIdx.x * blockDim.x + threadIdx.x;
    if (i < n) g_hist[i] = 0;
}
__global__ void hist_kernel(const int* __restrict__ col, int E) {
    int i = blockIdx.x * blockDim.x + threadIdx.x;
    if (i < E) atomicAdd(&g_hist[col[i]], 1);
}
__global__ void scan1(int n) {
    __shared__ int s[512];
    int i = blockIdx.x * 512 + threadIdx.x;
    s[threadIdx.x] = (i < n) ? g_hist[i] : 0;
    __syncthreads();
    for (int off = 256; off > 0; off >>= 1) {
        if (threadIdx.x < off) s[threadIdx.x] += s[threadIdx.x + off];
        __syncthreads();
    }
    if (threadIdx.x == 0) g_bsum[blockIdx.x] = s[0];
}
__global__ void scan2(int nch) {
    if (threadIdx.x == 0) {
        int run = 0;
        for (int i = 0; i < nch; i++) { int v = g_bsum[i]; g_bsum[i] = run; run += v; }
    }
}
__global__ void scan3(int n) {
    __shared__ int s[512];
    int i = blockIdx.x * 512 + threadIdx.x;
    int v = (i < n) ? g_hist[i] : 0;
    s[threadIdx.x] = v;
    __syncthreads();
    for (int off = 1; off < 512; off <<= 1) {
        int t = (threadIdx.x >= off) ? s[threadIdx.x - off] : 0;
        __syncthreads();
        s[threadIdx.x] += t;
        __syncthreads();
    }
    if (i < n) {
        int excl = s[threadIdx.x] - v + g_bsum[blockIdx.x];
        g_cursor[i] = excl;
        g_deg[i] = (float)v;
    }
}
__global__ void sort_scatter(const int* __restrict__ row, const int* __restrict__ col, int E) {
    int i = blockIdx.x * blockDim.x + threadIdx.x;
    if (i < E) {
        int c = col[i];
        int pos = atomicAdd(&g_cursor[c], 1);
        g_eRowS[pos] = row[i];
        g_eColS[pos] = c;
    }
}

// ---------------- small utility kernels ----------------
__global__ void zero2_kernel(float* p1, int n1, float* p2, int n2) {
    int i = blockIdx.x * blockDim.x + threadIdx.x;
    if (i < n1) p1[i] = 0.0f;
    if (i < n2) p2[i] = 0.0f;
}
__global__ void copy_kernel(const float* __restrict__ s, float* d, int n) {
    int i = blockIdx.x * blockDim.x + threadIdx.x;
    if (i < n) d[i] = s[i];
}

// ---------------- generic node GEMM: out = act(A@W + bias) ----------------
__global__ __launch_bounds__(NT, 2) void gemm_mma(
    const float* __restrict__ A, int K,
    const uint32_t* __restrict__ Wtf,
    const float* __restrict__ bias,
    float* __restrict__ out, int n, int act)
{
    extern __shared__ char smem[];
    uint32_t* sA = (uint32_t*)smem;
    uint32_t sbase = smem_u32(smem);
    int tid = threadIdx.x, wid = tid >> 5, lane = tid & 31;
    int warpM = wid & 3, warpN = wid >> 2;
    int m0 = blockIdx.x * 128;

    if (K == 128) {
        for (int idx = tid; idx < 4096; idx += NT) {
            int m = idx >> 5, q = idx & 31;
            int gm = m0 + m; if (gm >= n) gm = n - 1;
            float4 v = ((const float4*)A)[(size_t)gm * 32 + q];
            uint4 t = {f2tf(v.x), f2tf(v.y), f2tf(v.z), f2tf(v.w)};
            *(uint4*)(sA + m * STRA + q * 4) = t;
        }
    } else {  // K == 64
        for (int idx = tid; idx < 2048; idx += NT) {
            int m = idx >> 4, q = idx & 15;
            int gm = m0 + m; if (gm >= n) gm = n - 1;
            float4 v = ((const float4*)A)[(size_t)gm * 16 + q];
            uint4 t = {f2tf(v.x), f2tf(v.y), f2tf(v.z), f2tf(v.w)};
            *(uint4*)(sA + m * STRA + q * 4) = t;
        }
    }
    float acc[2][8][4];
    acc_zero(acc);
    pipe_gemm(sbase, sbase + SB0_OFF, sbase + SB1_OFF,
              Wtf, K, K >> 5, tid, warpM, warpN, lane, false, acc);

    int l4 = lane >> 2, q2 = (lane & 3) * 2;
#pragma unroll
    for (int mi = 0; mi < 2; mi++)
#pragma unroll
        for (int half = 0; half < 2; half++) {
            int gm = m0 + warpM * 32 + mi * 16 + l4 + half * 8;
            if (gm >= n) continue;
            float* orow = out + (size_t)gm * 128;
#pragma unroll
            for (int ni = 0; ni < 8; ni++) {
                int c = warpN * 64 + ni * 8 + q2;
                float v0 = acc[mi][ni][half * 2 + 0];
                float v1 = acc[mi][ni][half * 2 + 1];
                if (bias) { float2 bv = *(const float2*)(bias + c); v0 += bv.x; v1 += bv.y; }
                if (act)  { v0 = silu(v0); v1 = silu(v1); }
                *(float2*)(orow + c) = make_float2(v0, v1);
            }
        }
}

// ---------------- dual projection (layer 0 only) ----------------
__global__ __launch_bounds__(NT, 2) void proj2(
    const float* __restrict__ A,
    const uint32_t* __restrict__ Wa, const uint32_t* __restrict__ Wb,
    float* __restrict__ outA, float* __restrict__ outB, int n)
{
    extern __shared__ char smem[];
    uint32_t* sA = (uint32_t*)smem;
    uint32_t sbase = smem_u32(smem);
    int tid = threadIdx.x, wid = tid >> 5, lane = tid & 31;
    int warpM = wid & 3, warpN = wid >> 2;
    int m0 = blockIdx.x * 128;

    for (int idx = tid; idx < 4096; idx += NT) {
        int m = idx >> 5, q = idx & 31;
        int gm = m0 + m; if (gm >= n) gm = n - 1;
        float4 v = ((const float4*)A)[(size_t)gm * 32 + q];
        uint4 t = {f2tf(v.x), f2tf(v.y), f2tf(v.z), f2tf(v.w)};
        *(uint4*)(sA + m * STRA + q * 4) = t;
    }
    float acc[2][8][4];
    int l4 = lane >> 2, q2 = (lane & 3) * 2;

    acc_zero(acc);
    pipe_gemm(sbase, sbase + SB0_OFF, sbase + SB1_OFF,
              Wa, 128, 4, tid, warpM, warpN, lane, false, acc);
    prefetch_chunk(sbase + SB0_OFF, Wb, 128, 0, tid);
#pragma unroll
    for (int mi = 0; mi < 2; mi++)
#pragma unroll
        for (int half = 0; half < 2; half++) {
            int gm = m0 + warpM * 32 + mi * 16 + l4 + half * 8;
            if (gm >= n) continue;
            float* orow = outA + (size_t)gm * 128;
#pragma unroll
            for (int ni = 0; ni < 8; ni++) {
                int c = warpN * 64 + ni * 8 + q2;
                *(float2*)(orow + c) = make_float2(acc[mi][ni][half*2+0], acc[mi][ni][half*2+1]);
            }
        }
    acc_zero(acc);
    pipe_gemm(sbase, sbase + SB0_OFF, sbase + SB1_OFF,
              Wb, 128, 4, tid, warpM, warpN, lane, true, acc);
#pragma unroll
    for (int mi = 0; mi < 2; mi++)
#pragma unroll
        for (int half = 0; half < 2; half++) {
            int gm = m0 + warpM * 32 + mi * 16 + l4 + half * 8;
            if (gm >= n) continue;
            float* orow = outB + (size_t)gm * 128;
#pragma unroll
            for (int ni = 0; ni < 8; ni++) {
                int c = warpN * 64 + ni * 8 + q2;
                *(float2*)(orow + c) = make_float2(acc[mi][ni][half*2+0], acc[mi][ni][half*2+1]);
            }
        }
}

// ---- fused node MLP + LN + next-layer projections (+ optional eps zero) ----
__global__ __launch_bounds__(NT, 2) void node_mlp_ln_proj(
    const float* __restrict__ aggIn,
    const uint32_t* __restrict__ Wa, const uint32_t* __restrict__ Wb,
    const float* __restrict__ b1,
    const uint32_t* __restrict__ W2tf, const float* __restrict__ b2,
    const float* __restrict__ lng, const float* __restrict__ lnb,
    float* __restrict__ h, float* __restrict__ x,
    const float* __restrict__ cup, const float* __restrict__ deg,
    const uint32_t* __restrict__ WaN, const uint32_t* __restrict__ WbN,
    float* __restrict__ outA, float* __restrict__ outB,
    float* __restrict__ epsZ, int n)
{
    extern __shared__ char smem[];
    uint32_t* sA = (uint32_t*)smem;
    float* sSum = (float*)(smem + SMEM_AB);
    float* sSq  = (float*)(smem + SMEM_AB + 512);
    uint32_t sbase = smem_u32(smem);
    int tid = threadIdx.x, wid = tid >> 5, lane = tid & 31;
    int warpM = wid & 3, warpN = wid >> 2;
    int m0 = blockIdx.x * 128;
    int l4 = lane >> 2, q2 = (lane & 3) * 2;

    if (tid < 128) { sSum[tid] = 0.0f; sSq[tid] = 0.0f; }
    // sA = f2tf(h)
    for (int idx = tid; idx < 4096; idx += NT) {
        int m = idx >> 5, q = idx & 31;
        int gm = m0 + m; if (gm >= n) gm = n - 1;
        float4 v = ((const float4*)h)[(size_t)gm * 32 + q];
        uint4 t = {f2tf(v.x), f2tf(v.y), f2tf(v.z), f2tf(v.w)};
        *(uint4*)(sA + m * STRA + q * 4) = t;
    }
    float acc[2][8][4];
    acc_zero(acc);
    pipe_gemm(sbase, sbase + SB0_OFF, sbase + SB1_OFF,
              Wa, 128, 4, tid, warpM, warpN, lane, false, acc);
    prefetch_chunk(sbase + SB0_OFF, Wb, 128, 0, tid);
    // sA = f2tf(agg)
    for (int idx = tid; idx < 4096; idx += NT) {
        int m = idx >> 5, q = idx & 31;
        int gm = m0 + m; if (gm >= n) gm = n - 1;
        float4 v = ((const float4*)aggIn)[(size_t)gm * 32 + q];
        uint4 t = {f2tf(v.x), f2tf(v.y), f2tf(v.z), f2tf(v.w)};
        *(uint4*)(sA + m * STRA + q * 4) = t;
    }
    __syncthreads();
    pipe_gemm(sbase, sbase + SB0_OFF, sbase + SB1_OFF,
              Wb, 128, 4, tid, warpM, warpN, lane, true, acc);   // acc = h@Wa + agg@Wb

    prefetch_chunk(sbase + SB0_OFF, W2tf, 128, 0, tid);

    // u = silu(acc + b1) -> sA (tf32)
#pragma unroll
    for (int mi = 0; mi < 2; mi++)
#pragma unroll
        for (int half = 0; half < 2; half++) {
            int rl = warpM * 32 + mi * 16 + l4 + half * 8;
#pragma unroll
            for (int ni = 0; ni < 8; ni++) {
                int c = warpN * 64 + ni * 8 + q2;
                float2 bv = *(const float2*)(b1 + c);
                uint2 t;
                t.x = f2tf(silu(acc[mi][ni][half*2+0] + bv.x));
                t.y = f2tf(silu(acc[mi][ni][half*2+1] + bv.y));
                *(uint2*)(sA + rl * STRA + c) = t;
            }
        }
    __syncthreads();
    acc_zero(acc);
    pipe_gemm(sbase, sbase + SB0_OFF, sbase + SB1_OFF,
              W2tf, 128, 4, tid, warpM, warpN, lane, true, acc);   // acc = u @ W2

    // phase 1: val = h + acc + b2 -> overwrite h (pre-LN); row sums
#pragma unroll
    for (int mi = 0; mi < 2; mi++)
#pragma unroll
        for (int half = 0; half < 2; half++) {
            int rl = warpM * 32 + mi * 16 + l4 + half * 8;
            int gm = m0 + rl;
            float s = 0.0f, s2 = 0.0f;
            if (gm < n) {
                float* hrow = h + (size_t)gm * 128;
#pragma unroll
                for (int ni = 0; ni < 8; ni++) {
                    int c = warpN * 64 + ni * 8 + q2;
                    float2 bv = *(const float2*)(b2 + c);
                    float2 hv = *(const float2*)(hrow + c);
                    float v0 = acc[mi][ni][half*2+0] + bv.x + hv.x;
                    float v1 = acc[mi][ni][half*2+1] + bv.y + hv.y;
                    *(float2*)(hrow + c) = make_float2(v0, v1);
                    s += v0 + v1; s2 += v0*v0 + v1*v1;
                }
            }
            s  += __shfl_xor_sync(0xffffffffu, s, 1);
            s  += __shfl_xor_sync(0xffffffffu, s, 2);
            s2 += __shfl_xor_sync(0xffffffffu, s2, 1);
            s2 += __shfl_xor_sync(0xffffffffu, s2, 2);
            if ((lane & 3) == 0 && gm < n) {
                atomicAdd(&sSum[rl], s);
                atomicAdd(&sSq[rl], s2);
            }
        }
    __syncthreads();
    // phase 2: normalize; write h AND stage tf32(h_new) into sA
    for (int idx = tid; idx < 16384; idx += NT) {
        int rl = idx >> 7, c = idx & 127;
        int gm = m0 + rl;
        float outv = 0.0f;
        if (gm < n) {
            float mu = sSum[rl] * (1.0f / 128.0f);
            float var = sSq[rl] * (1.0f / 128.0f) - mu * mu;
            float val = h[(size_t)gm * 128 + c];
            outv = (val - mu) * rsqrtf(var + 1e-5f) * lng[c] + lnb[c];
            h[(size_t)gm * 128 + c] = outv;
        }
        sA[rl * STRA + c] = f2tf(outv);
    }
    if (tid < 128) {
        int gm = m0 + tid;
        if (gm < n) {
            float inv = __fdividef(1.0f, deg[gm] + 1.0f);
            x[gm*3 + 0] += cup[gm*3 + 0] * inv;
            x[gm*3 + 1] += cup[gm*3 + 1] * inv;
            x[gm*3 + 2] += cup[gm*3 + 2] * inv;
            if (epsZ) {
                epsZ[gm*3 + 0] = 0.0f;
                epsZ[gm*3 + 1] = 0.0f;
                epsZ[gm*3 + 2] = 0.0f;
            }
        }
    }
    // next-layer projections from the staged LN'd tile
    acc_zero(acc);
    pipe_gemm(sbase, sbase + SB0_OFF, sbase + SB1_OFF,
              WaN, 128, 4, tid, warpM, warpN, lane, false, acc);
    prefetch_chunk(sbase + SB0_OFF, WbN, 128, 0, tid);
#pragma unroll
    for (int mi = 0; mi < 2; mi++)
#pragma unroll
        for (int half = 0; half < 2; half++) {
            int gm = m0 + warpM * 32 + mi * 16 + l4 + half * 8;
            if (gm >= n) continue;
            float* orow = outA + (size_t)gm * 128;
#pragma unroll
            for (int ni = 0; ni < 8; ni++) {
                int c = warpN * 64 + ni * 8 + q2;
                *(float2*)(orow + c) = make_float2(acc[mi][ni][half*2+0], acc[mi][ni][half*2+1]);
            }
        }
    acc_zero(acc);
    pipe_gemm(sbase, sbase + SB0_OFF, sbase + SB1_OFF,
              WbN, 128, 4, tid, warpM, warpN, lane, true, acc);
#pragma unroll
    for (int mi = 0; mi < 2; mi++)
#pragma unroll
        for (int half = 0; half < 2; half++) {
            int gm = m0 + warpM * 32 + mi * 16 + l4 + half * 8;
            if (gm >= n) continue;
            float* orow = outB + (size_t)gm * 128;
#pragma unroll
            for (int ni = 0; ni < 8; ni++) {
                int c = warpN * 64 + ni * 8 + q2;
                *(float2*)(orow + c) = make_float2(acc[mi][ni][half*2+0], acc[mi][ni][half*2+1]);
            }
        }
}

// ---------------- fused eps node head: eps += silu(h@W + x@w1x3 + b1) @ W2 + b2 ----------------
__global__ __launch_bounds__(NT, 2) void gemm_eps(
    const float* __restrict__ h,
    const uint32_t* __restrict__ Wtf,
    const float* __restrict__ xin,
    const float* __restrict__ w1x3,
    const float* __restrict__ b1,
    const float* __restrict__ W2,
    const float* __restrict__ b2,
    float* __restrict__ eps, int n)
{
    extern __shared__ char smem[];
    uint32_t* sA = (uint32_t*)smem;
    float* sPart = (float*)(smem + SMEM_AB);   // 384 floats
    uint32_t sbase = smem_u32(smem);
    int tid = threadIdx.x, wid = tid >> 5, lane = tid & 31;
    int warpM = wid & 3, warpN = wid >> 2;
    int m0 = blockIdx.x * 128;
    int l4 = lane >> 2, q2 = (lane & 3) * 2;

    for (int i = tid; i < 384; i += NT) sPart[i] = 0.0f;
    for (int idx = tid; idx < 4096; idx += NT) {
        int m = idx >> 5, q = idx & 31;
        int gm = m0 + m; if (gm >= n) gm = n - 1;
        float4 v = ((const float4*)h)[(size_t)gm * 32 + q];
        uint4 t = {f2tf(v.x), f2tf(v.y), f2tf(v.z), f2tf(v.w)};
        *(uint4*)(sA + m * STRA + q * 4) = t;
    }
    float acc[2][8][4];
    acc_zero(acc);
    pipe_gemm(sbase, sbase + SB0_OFF, sbase + SB1_OFF,
              Wtf, 128, 4, tid, warpM, warpN, lane, false, acc);

    float p0[2][2], p1[2][2], p2[2][2];
#pragma unroll
    for (int mi = 0; mi < 2; mi++)
#pragma unroll
        for (int half = 0; half < 2; half++) {
            p0[mi][half] = 0.0f; p1[mi][half] = 0.0f; p2[mi][half] = 0.0f;
            int gm = m0 + warpM * 32 + mi * 16 + l4 + half * 8;
            if (gm >= n) continue;
            float x0 = xin[gm*3], x1 = xin[gm*3+1], x2 = xin[gm*3+2];
#pragma unroll
            for (int ni = 0; ni < 8; ni++) {
                int c = warpN * 64 + ni * 8 + q2;
#pragma unroll
                for (int j = 0; j < 2; j++) {
                    int cc = c + j;
                    float v = acc[mi][ni][half*2+j]
                            + x0*w1x3[cc] + x1*w1x3[128+cc] + x2*w1x3[256+cc] + b1[cc];
                    float s = silu(v);
                    p0[mi][half] += s * W2[cc*3 + 0];
                    p1[mi][half] += s * W2[cc*3 + 1];
                    p2[mi][half] += s * W2[cc*3 + 2];
                }
            }
        }
#pragma unroll
    for (int mi = 0; mi < 2; mi++)
#pragma unroll
        for (int half = 0; half < 2; half++) {
            p0[mi][half] += __shfl_xor_sync(0xffffffffu, p0[mi][half], 1);
            p0[mi][half] += __shfl_xor_sync(0xffffffffu, p0[mi][half], 2);
            p1[mi][half] += __shfl_xor_sync(0xffffffffu, p1[mi][half], 1);
            p1[mi][half] += __shfl_xor_sync(0xffffffffu, p1[mi][half], 2);
            p2[mi][half] += __shfl_xor_sync(0xffffffffu, p2[mi][half], 1);
            p2[mi][half] += __shfl_xor_sync(0xffffffffu, p2[mi][half], 2);
        }
    if ((lane & 3) == 0) {
#pragma unroll
        for (int mi = 0; mi < 2; mi++)
#pragma unroll
            for (int half = 0; half < 2; half++) {
                int rl = warpM * 32 + mi * 16 + l4 + half * 8;
                atomicAdd(&sPart[rl*3 + 0], p0[mi][half]);
                atomicAdd(&sPart[rl*3 + 1], p1[mi][half]);
                atomicAdd(&sPart[rl*3 + 2], p2[mi][half]);
            }
    }
    __syncthreads();
    if (tid < 128) {
        int gm = m0 + tid;
        if (gm < n) {
            eps[gm*3 + 0] += sPart[tid*3 + 0] + b2[0];
            eps[gm*3 + 1] += sPart[tid*3 + 1] + b2[1];
            eps[gm*3 + 2] += sPart[tid*3 + 2] + b2[2];
        }
    }
}

// ---------------- edge aux layout ----------------
#define AUX_ROW   0
#define AUX_COL   512
#define AUX_VAL   1024
#define AUX_DIST  1536
#define AUX_RELX  2048
#define AUX_RELY  2560
#define AUX_RELZ  3072
#define AUX_PART  3584
#define AUX_SEG   5120
#define AUX_NSEG  5648
#define AUX_WTOT  5652
#define AUX_SIZE  5696

__device__ __forceinline__ void build_segments(char* aux, int tid, int wid, int lane) {
    int* sCol = (int*)(aux + AUX_COL);
    int* sSeg = (int*)(aux + AUX_SEG);
    int* sNseg = (int*)(aux + AUX_NSEG);
    int* sW = (int*)(aux + AUX_WTOT);
    int flag = 0, pre = 0;
    if (tid < 128) {
        flag = (tid == 0) || (sCol[tid] != sCol[tid - 1]);
        unsigned bm = __ballot_sync(0xffffffffu, flag);
        pre = __popc(bm & ((1u << lane) - 1));
        if (lane == 0) sW[wid] = __popc(bm);
    }
    __syncthreads();
    if (tid < 128 && flag) {
        int off = 0;
        for (int w = 0; w < wid; w++) off += sW[w];
        sSeg[off + pre] = tid;
    }
    if (tid == 0) {
        int t = sW[0] + sW[1] + sW[2] + sW[3];
        sNseg[0] = t;
        sSeg[t] = 128;
    }
    __syncthreads();
}

// ---------------- fused edge kernel (message-passing layer) ----------------
__global__ __launch_bounds__(NT, 2) void edge_layer_mma(
    const int* __restrict__ eRow, const int* __restrict__ eCol, int E,
    const float* __restrict__ x,
    const float* __restrict__ hA, const float* __restrict__ hB,
    const float* __restrict__ w1c, const float* __restrict__ b1,
    const uint32_t* __restrict__ W2tf, const float* __restrict__ b2,
    const uint32_t* __restrict__ Cw1tf, const float* __restrict__ cb1,
    const float* __restrict__ cw2,
    float* __restrict__ agg, float* __restrict__ cupd)
{
    extern __shared__ char smem[];
    uint32_t* sA = (uint32_t*)smem;
    char* aux = smem + SMEM_AB;
    int*   sRow   = (int*)(aux + AUX_ROW);
    int*   sCol   = (int*)(aux + AUX_COL);
    int*   sValid = (int*)(aux + AUX_VAL);
    float* sDist  = (float*)(aux + AUX_DIST);
    float* sRelx  = (float*)(aux + AUX_RELX);
    float* sRely  = (float*)(aux + AUX_RELY);
    float* sRelz  = (float*)(aux + AUX_RELZ);
    float* sPart  = (float*)(aux + AUX_PART);
    int*   sSeg   = (int*)(aux + AUX_SEG);
    int*   sNseg  = (int*)(aux + AUX_NSEG);
    uint32_t sbase = smem_u32(smem);

    int tid = threadIdx.x, wid = tid >> 5, lane = tid & 31;
    int warpM = wid & 3, warpN = wid >> 2;
    int e0 = blockIdx.x * 128;

    prefetch_chunk(sbase + SB0_OFF, W2tf, 128, 0, tid);

    if (tid < 128) {
        sPart[tid] = 0.0f;
        int e = e0 + tid;
        int valid = (e < E); if (!valid) e = E - 1;
        int r = eRow[e], c = eCol[e];
        float rx = x[r*3]   - x[c*3];
        float ry = x[r*3+1] - x[c*3+1];
        float rz = x[r*3+2] - x[c*3+2];
        float d = sqrtf(rx*rx + ry*ry + rz*rz);
        sRow[tid] = r; sCol[tid] = c; sValid[tid] = valid;
        sDist[tid] = d; sRelx[tid] = rx; sRely[tid] = ry; sRelz[tid] = rz;
    }
    __syncthreads();
    build_segments(aux, tid, wid, lane);

    {   // sA[e][k] = silu(t1), two threads per edge
        int e = tid >> 1, j0 = (tid & 1) * 64;
        int r = sRow[e], c = sCol[e];
        float d = sDist[e];
        const float4* pa  = (const float4*)(hA  + (size_t)r * 128 + j0);
        const float4* pb  = (const float4*)(hB  + (size_t)c * 128 + j0);
        const float4* pw  = (const float4*)(w1c + j0);
        const float4* pb1 = (const float4*)(b1  + j0);
        uint32_t* dst = sA + e * STRA + j0;
#pragma unroll
        for (int q = 0; q < 16; q++) {
            float4 a = pa[q], b = pb[q], w = pw[q], bb = pb1[q];
            uint4 v;
            v.x = f2tf(silu(a.x + b.x + d * w.x + bb.x));
            v.y = f2tf(silu(a.y + b.y + d * w.y + bb.y));
            v.z = f2tf(silu(a.z + b.z + d * w.z + bb.z));
            v.w = f2tf(silu(a.w + b.w + d * w.w + bb.w));
            *(uint4*)(dst + q * 4) = v;
        }
    }
    __syncthreads();

    float acc[2][8][4];
    acc_zero(acc);
    pipe_gemm(sbase, sbase + SB0_OFF, sbase + SB1_OFF,
              W2tf, 128, 4, tid, warpM, warpN, lane, true, acc);   // D1 = U @ m_w2

    prefetch_chunk(sbase + SB0_OFF, Cw1tf, 128, 0, tid);

    int l4 = lane >> 2, q2 = (lane & 3) * 2;
    {   // msg = silu(D1 + b2) into sA (zero invalid rows)
        float2 bv[8];
#pragma unroll
        for (int ni = 0; ni < 8; ni++) bv[ni] = *(const float2*)(b2 + warpN * 64 + ni * 8 + q2);
#pragma unroll
        for (int mi = 0; mi < 2; mi++)
#pragma unroll
            for (int half = 0; half < 2; half++) {
                int e = warpM * 32 + mi * 16 + l4 + half * 8;
                float vscale = sValid[e] ? 1.0f : 0.0f;
#pragma unroll
                for (int ni = 0; ni < 8; ni++) {
                    int c = warpN * 64 + ni * 8 + q2;
                    float m0 = silu(acc[mi][ni][half*2+0] + bv[ni].x) * vscale;
                    float m1 = silu(acc[mi][ni][half*2+1] + bv[ni].y) * vscale;
                    uint2 t; t.x = f2tf(m0); t.y = f2tf(m1);
                    *(uint2*)(sA + e * STRA + c) = t;
                }
            }
    }
    __syncthreads();
    acc_zero(acc);
    pipe_gemm(sbase, sbase + SB0_OFF, sbase + SB1_OFF,
              Cw1tf, 128, 4, tid, warpM, warpN, lane, true, acc);   // D2 = msg @ c_w1

    float2 cbv[8], cwv[8];
#pragma unroll
    for (int ni = 0; ni < 8; ni++) {
        int c = warpN * 64 + ni * 8 + q2;
        cbv[ni] = *(const float2*)(cb1 + c);
        cwv[ni] = *(const float2*)(cw2 + c);
    }
    float p[2][2];
    p[0][0] = p[0][1] = p[1][0] = p[1][1] = 0.0f;
#pragma unroll
    for (int ni = 0; ni < 8; ni++)
#pragma unroll
        for (int mi = 0; mi < 2; mi++)
#pragma unroll
            for (int half = 0; half < 2; half++)
                p[mi][half] += silu(acc[mi][ni][half*2+0] + cbv[ni].x) * cwv[ni].x
                             + silu(acc[mi][ni][half*2+1] + cbv[ni].y) * cwv[ni].y;
#pragma unroll
    for (int mi = 0; mi < 2; mi++)
#pragma unroll
        for (int half = 0; half < 2; half++) {
            p[mi][half] += __shfl_xor_sync(0xffffffffu, p[mi][half], 1);
            p[mi][half] += __shfl_xor_sync(0xffffffffu, p[mi][half], 2);
        }
    if ((lane & 3) == 0) {
#pragma unroll
        for (int mi = 0; mi < 2; mi++)
#pragma unroll
            for (int half = 0; half < 2; half++)
                atomicAdd(&sPart[warpM * 32 + mi * 16 + l4 + half * 8], p[mi][half]);
    }
    __syncthreads();

    int nseg = sNseg[0];
    {   // segmented agg reduction
        int c = tid & 127, grp = tid >> 7;
        for (int s = grp; s < nseg; s += 2) {
            int st = sSeg[s], en = sSeg[s + 1];
            float a = 0.0f;
            for (int e = st; e < en; e++) a += __uint_as_float(sA[e * STRA + c]);
            red1(agg + (size_t)sCol[st] * 128 + c, a);
        }
    }
    if (tid < nseg) {
        int st = sSeg[tid], en = sSeg[tid + 1];
        float ax = 0, ay = 0, az = 0;
        for (int e = st; e < en; e++) {
            if (!sValid[e]) continue;
            float cm = tanh_ap(sPart[e]);
            float f = __fdividef(cm, sDist[e] + 1e-8f);
            ax += f * sRelx[e]; ay += f * sRely[e]; az += f * sRelz[e];
        }
        int cN = sCol[st];
        red1(cupd + cN*3 + 0, ax);
        red1(cupd + cN*3 + 1, ay);
        red1(cupd + cN*3 + 2, az);
    }
}

// ---------------- fused edge kernel (epsilon head) ----------------
__global__ __launch_bounds__(NT, 2) void edge_eps_mma(
    const int* __restrict__ eRow, const int* __restrict__ eCol, int E,
    const float* __restrict__ x,
    const float* __restrict__ hA, const float* __restrict__ hB,
    const float* __restrict__ wRel, const float* __restrict__ b1,
    const uint32_t* __restrict__ W2tf, const float* __restrict__ b2,
    const uint32_t* __restrict__ Cw1tf, const float* __restrict__ cb1,
    const float* __restrict__ cw2, const float* __restrict__ cb2,
    float* __restrict__ eps)
{
    extern __shared__ char smem[];
    uint32_t* sA = (uint32_t*)smem;
    char* aux = smem + SMEM_AB;
    int*   sRow   = (int*)(aux + AUX_ROW);
    int*   sCol   = (int*)(aux + AUX_COL);
    int*   sValid = (int*)(aux + AUX_VAL);
    float* sDist  = (float*)(aux + AUX_DIST);
    float* sRelx  = (float*)(aux + AUX_RELX);
    float* sRely  = (float*)(aux + AUX_RELY);
    float* sRelz  = (float*)(aux + AUX_RELZ);
    float* sPart  = (float*)(aux + AUX_PART);
    int*   sSeg   = (int*)(aux + AUX_SEG);
    int*   sNseg  = (int*)(aux + AUX_NSEG);
    uint32_t sbase = smem_u32(smem);

    int tid = threadIdx.x, wid = tid >> 5, lane = tid & 31;
    int warpM = wid & 3, warpN = wid >> 2;
    int e0 = blockIdx.x * 128;

    prefetch_chunk(sbase + SB0_OFF, W2tf, 128, 0, tid);

    for (int i = tid; i < 384; i += NT) sPart[i] = 0.0f;
    if (tid < 128) {
        int e = e0 + tid;
        int valid = (e < E); if (!valid) e = E - 1;
        int r = eRow[e], c = eCol[e];
        float rx = x[r*3]   - x[c*3];
        float ry = x[r*3+1] - x[c*3+1];
        float rz = x[r*3+2] - x[c*3+2];
        float d = sqrtf(rx*rx + ry*ry + rz*rz);
        sRow[tid] = r; sCol[tid] = c; sValid[tid] = valid;
        sDist[tid] = d; sRelx[tid] = rx; sRely[tid] = ry; sRelz[tid] = rz;
    }
    __syncthreads();
    build_segments(aux, tid, wid, lane);

    {
        int e = tid >> 1, j0 = (tid & 1) * 64;
        int r = sRow[e], c = sCol[e];
        float d = sDist[e], rx = sRelx[e], ry = sRely[e], rz = sRelz[e];
        const float4* pa  = (const float4*)(hA + (size_t)r * 128 + j0);
        const float4* pb  = (const float4*)(hB + (size_t)c * 128 + j0);
        const float4* pwx = (const float4*)(wRel + j0);
        const float4* pwy = (const float4*)(wRel + 128 + j0);
        const float4* pwz = (const float4*)(wRel + 256 + j0);
        const float4* pwd = (const float4*)(wRel + 384 + j0);
        const float4* pb1 = (const float4*)(b1 + j0);
        uint32_t* dst = sA + e * STRA + j0;
#pragma unroll
        for (int q = 0; q < 16; q++) {
            float4 a = pa[q], b = pb[q];
            float4 wx = pwx[q], wy = pwy[q], wz = pwz[q], wd = pwd[q], bb = pb1[q];
            uint4 v;
            v.x = f2tf(silu(a.x + b.x + rx*wx.x + ry*wy.x + rz*wz.x + d*wd.x + bb.x));
            v.y = f2tf(silu(a.y + b.y + rx*wx.y + ry*wy.y + rz*wz.y + d*wd.y + bb.y));
            v.z = f2tf(silu(a.z + b.z + rx*wx.z + ry*wy.z + rz*wz.z + d*wd.z + bb.z));
            v.w = f2tf(silu(a.w + b.w + rx*wx.w + ry*wy.w + rz*wz.w + d*wd.w + bb.w));
            *(uint4*)(dst + q * 4) = v;
        }
    }
    __syncthreads();

    float acc[2][8][4];
    acc_zero(acc);
    pipe_gemm(sbase, sbase + SB0_OFF, sbase + SB1_OFF,
              W2tf, 128, 4, tid, warpM, warpN, lane, true, acc);

    prefetch_chunk(sbase + SB0_OFF, Cw1tf, 128, 0, tid);

    int l4 = lane >> 2, q2 = (lane & 3) * 2;
    {
        float2 bv[8];
#pragma unroll
        for (int ni = 0; ni < 8; ni++) bv[ni] = *(const float2*)(b2 + warpN * 64 + ni * 8 + q2);
#pragma unroll
        for (int mi = 0; mi < 2; mi++)
#pragma unroll
            for (int half = 0; half < 2; half++) {
                int e = warpM * 32 + mi * 16 + l4 + half * 8;
#pragma unroll
                for (int ni = 0; ni < 8; ni++) {
                    int c = warpN * 64 + ni * 8 + q2;
                    uint2 t;
                    t.x = f2tf(silu(acc[mi][ni][half*2+0] + bv[ni].x));
                    t.y = f2tf(silu(acc[mi][ni][half*2+1] + bv[ni].y));
                    *(uint2*)(sA + e * STRA + c) = t;
                }
            }
    }
    __syncthreads();
    acc_zero(acc);
    pipe_gemm(sbase, sbase + SB0_OFF, sbase + SB1_OFF,
              Cw1tf, 128, 4, tid, warpM, warpN, lane, true, acc);

    float p0[2][2], p1[2][2], p2[2][2];
#pragma unroll
    for (int mi = 0; mi < 2; mi++)
#pragma unroll
        for (int half = 0; half < 2; half++) {
            p0[mi][half] = 0.0f; p1[mi][half] = 0.0f; p2[mi][half] = 0.0f;
        }
#pragma unroll
    for (int ni = 0; ni < 8; ni++) {
        int c = warpN * 64 + ni * 8 + q2;
        float2 cbv = *(const float2*)(cb1 + c);
        float w00 = cw2[c*3+0], w01 = cw2[c*3+1], w02 = cw2[c*3+2];
        float w10 = cw2[c*3+3], w11 = cw2[c*3+4], w12 = cw2[c*3+5];
#pragma unroll
        for (int mi = 0; mi < 2; mi++)
#pragma unroll
            for (int half = 0; half < 2; half++) {
                float v0 = silu(acc[mi][ni][half*2+0] + cbv.x);
                float v1 = silu(acc[mi][ni][half*2+1] + cbv.y);
                p0[mi][half] += v0*w00 + v1*w10;
                p1[mi][half] += v0*w01 + v1*w11;
                p2[mi][half] += v0*w02 + v1*w12;
            }
    }
#pragma unroll
    for (int mi = 0; mi < 2; mi++)
#pragma unroll
        for (int half = 0; half < 2; half++) {
            p0[mi][half] += __shfl_xor_sync(0xffffffffu, p0[mi][half], 1);
            p0[mi][half] += __shfl_xor_sync(0xffffffffu, p0[mi][half], 2);
            p1[mi][half] += __shfl_xor_sync(0xffffffffu, p1[mi][half], 1);
            p1[mi][half] += __shfl_xor_sync(0xffffffffu, p1[mi][half], 2);
            p2[mi][half] += __shfl_xor_sync(0xffffffffu, p2[mi][half], 1);
            p2[mi][half] += __shfl_xor_sync(0xffffffffu, p2[mi][half], 2);
        }
    if ((lane & 3) == 0) {
#pragma unroll
        for (int mi = 0; mi < 2; mi++)
#pragma unroll
            for (int half = 0; half < 2; half++) {
                int e = warpM * 32 + mi * 16 + l4 + half * 8;
                atomicAdd(&sPart[e*3 + 0], p0[mi][half]);
                atomicAdd(&sPart[e*3 + 1], p1[mi][half]);
                atomicAdd(&sPart[e*3 + 2], p2[mi][half]);
            }
    }
    __syncthreads();

    int nseg = sNseg[0];
    if (tid < nseg) {
        int st = sSeg[tid], en = sSeg[tid + 1];
        float a0 = 0, a1 = 0, a2 = 0; int cnt = 0;
        for (int e = st; e < en; e++) {
            if (!sValid[e]) continue;
            a0 += sPart[e*3 + 0]; a1 += sPart[e*3 + 1]; a2 += sPart[e*3 + 2];
            cnt++;
        }
        int cN = sCol[st];
        red1(eps + cN*3 + 0, a0 + cnt * cb2[0]);
        red1(eps + cN*3 + 1, a1 + cnt * cb2[1]);
        red1(eps + cN*3 + 2, a2 + cnt * cb2[2]);
    }
}

// ---------------- pack output: [h | x | eps] ----------------
__global__ void pack_kernel(const float* __restrict__ h, const float* __restrict__ x,
                            const float* __restrict__ eps, float* __restrict__ out, int n)
{
    int i = blockIdx.x * blockDim.x + threadIdx.x;
    int nh = n * 128;
    if (i < nh) out[i] = h[i];
    else if (i < nh + 3*n) out[i] = x[i - nh];
    else if (i < nh + 6*n) out[i] = eps[i - nh - 3*n];
}

// ---------------- host ----------------
static const int NODE_SMEM = SMEM_AB;
static const int LN_SMEM   = SMEM_AB + 1024;
static const int EPS_SMEM  = SMEM_AB + 1536;
static const int EDGE_SMEM = SMEM_AB + AUX_SIZE;

#define OFF_MW1A 0
#define OFF_MW1B 65536
#define OFF_MW2  131072
#define OFF_CW1  196608
#define OFF_NW1A 262144
#define OFF_NW1B 327680
#define OFF_NW2  393216
#define OFF_EMW1A 458752
#define OFF_EMW1B 475136
#define OFF_EMW2 491520
#define OFF_ECW1 507904
#define OFF_EHW1 524288
#define OFF_EMB  540672

extern "C" void kernel_launch(void* const* d_in, const int* in_sizes, int n_in,
                              void* d_out, int out_size)
{
    const float* in_h  = (const float*)d_in[0];
    const float* in_x  = (const float*)d_in[1];
    const int*   eidx  = (const int*)d_in[2];
    const float* emb_w = (const float*)d_in[3];
    const float* emb_b = (const float*)d_in[4];
    const float* m_w1  = (const float*)d_in[5];
    const float* m_b1  = (const float*)d_in[6];
    const float* m_w2  = (const float*)d_in[7];
    const float* m_b2  = (const float*)d_in[8];
    const float* c_w1  = (const float*)d_in[9];
    const float* c_b1  = (const float*)d_in[10];
    const float* c_w2  = (const float*)d_in[11];
    const float* n_w1  = (const float*)d_in[12];
    const float* n_b1  = (const float*)d_in[13];
    const float* n_w2  = (const float*)d_in[14];
    const float* n_b2  = (const float*)d_in[15];
    const float* ln_g  = (const float*)d_in[16];
    const float* ln_b  = (const float*)d_in[17];
    const float* em_w1 = (const float*)d_in[18];
    const float* em_b1 = (const float*)d_in[19];
    const float* em_w2 = (const float*)d_in[20];
    const float* em_b2 = (const float*)d_in[21];
    const float* ec_w1 = (const float*)d_in[22];
    const float* ec_b1 = (const float*)d_in[23];
    const float* ec_w2 = (const float*)d_in[24];
    const float* ec_b2 = (const float*)d_in[25];
    const float* eh_w1 = (const float*)d_in[26];
    const float* eh_b1 = (const float*)d_in[27];
    const float* eh_w2 = (const float*)d_in[28];
    const float* eh_b2 = (const float*)d_in[29];

    int n = in_sizes[0] / 64;
    int E = in_sizes[2] / 2;
    const int* eRow = eidx;
    const int* eCol = eidx + E;

    float *h, *x, *hA, *hB, *agg, *cup, *eps, *deg;
    uint32_t* wtf;
    int *eRowS, *eColS;
    cudaGetSymbolAddress((void**)&h,   g_h);
    cudaGetSymbolAddress((void**)&x,   g_x);
    cudaGetSymbolAddress((void**)&hA,  g_hA);
    cudaGetSymbolAddress((void**)&hB,  g_hB);
    cudaGetSymbolAddress((void**)&agg, g_agg);
    cudaGetSymbolAddress((void**)&cup, g_cup);
    cudaGetSymbolAddress((void**)&eps, g_eps);
    cudaGetSymbolAddress((void**)&deg, g_deg);
    cudaGetSymbolAddress((void**)&wtf, g_wtf);
    cudaGetSymbolAddress((void**)&eRowS, g_eRowS);
    cudaGetSymbolAddress((void**)&eColS, g_eColS);

    cudaFuncSetAttribute(gemm_mma,         cudaFuncAttributeMaxDynamicSharedMemorySize, NODE_SMEM);
    cudaFuncSetAttribute(proj2,            cudaFuncAttributeMaxDynamicSharedMemorySize, NODE_SMEM);
    cudaFuncSetAttribute(node_mlp_ln_proj, cudaFuncAttributeMaxDynamicSharedMemorySize, LN_SMEM);
    cudaFuncSetAttribute(gemm_eps,         cudaFuncAttributeMaxDynamicSharedMemorySize, EPS_SMEM);
    cudaFuncSetAttribute(edge_layer_mma,   cudaFuncAttributeMaxDynamicSharedMemorySize, EDGE_SMEM);
    cudaFuncSetAttribute(edge_eps_mma,     cudaFuncAttributeMaxDynamicSharedMemorySize, EDGE_SMEM);

    // weights -> tf32 n-major
    {
        CvtArgs a;
        int idx = 0;
        for (int i = 0; i < 4; i++) { a.src[idx] = m_w1 + (size_t)i*32896;          a.off[idx] = OFF_MW1A + i*16384; a.K[idx] = 128; idx++; }
        for (int i = 0; i < 4; i++) { a.src[idx] = m_w1 + (size_t)i*32896 + 16384;  a.off[idx] = OFF_MW1B + i*16384; a.K[idx] = 128; idx++; }
        for (int i = 0; i < 4; i++) { a.src[idx] = m_w2 + (size_t)i*16384;          a.off[idx] = OFF_MW2 + i*16384;  a.K[idx] = 128; idx++; }
        for (int i = 0; i < 4; i++) { a.src[idx] = c_w1 + (size_t)i*16384;          a.off[idx] = OFF_CW1 + i*16384;  a.K[idx] = 128; idx++; }
        for (int i = 0; i < 4; i++) { a.src[idx] = n_w1 + (size_t)i*32768;          a.off[idx] = OFF_NW1A + i*16384; a.K[idx] = 128; idx++; }
        for (int i = 0; i < 4; i++) { a.src[idx] = n_w1 + (size_t)i*32768 + 16384;  a.off[idx] = OFF_NW1B + i*16384; a.K[idx] = 128; idx++; }
        for (int i = 0; i < 4; i++) { a.src[idx] = n_w2 + (size_t)i*16384;          a.off[idx] = OFF_NW2 + i*16384;  a.K[idx] = 128; idx++; }
        a.src[idx] = em_w1;          a.off[idx] = OFF_EMW1A; a.K[idx] = 128; idx++;
        a.src[idx] = em_w1 + 16384;  a.off[idx] = OFF_EMW1B; a.K[idx] = 128; idx++;
        a.src[idx] = em_w2;          a.off[idx] = OFF_EMW2;  a.K[idx] = 128; idx++;
        a.src[idx] = ec_w1;          a.off[idx] = OFF_ECW1;  a.K[idx] = 128; idx++;
        a.src[idx] = eh_w1;          a.off[idx] = OFF_EHW1;  a.K[idx] = 128; idx++;
        a.src[idx] = emb_w;          a.off[idx] = OFF_EMB;   a.K[idx] = 64;  idx++;
        dim3 g(64, 34);
        cvt_kernel<<<g, 256>>>(a);
    }

    // counting sort of edges by col (also produces deg)
    int nch = (n + 511) / 512;
    zero_hist<<<(n + 255)/256, 256>>>(n);
    hist_kernel<<<(E + 255)/256, 256>>>(eCol, E);
    scan1<<<nch, 512>>>(n);
    scan2<<<1, 32>>>(nch);
    scan3<<<nch, 512>>>(n);
    sort_scatter<<<(E + 255)/256, 256>>>(eRow, eCol, E);

    int gN = (n + 127) / 128;
    int gE = (E + 127) / 128;

    gemm_mma<<<gN, NT, NODE_SMEM>>>(in_h, 64, wtf + OFF_EMB, emb_b, h, n, 0);
    copy_kernel<<<(3*n + 255)/256, 256>>>(in_x, x, 3*n);
    proj2<<<gN, NT, NODE_SMEM>>>(h, wtf + OFF_MW1A, wtf + OFF_MW1B, hA, hB, n);

    for (int i = 0; i < 4; i++) {
        zero2_kernel<<<(n*128 + 255)/256, 256>>>(agg, n*128, cup, 3*n);
        edge_layer_mma<<<gE, NT, EDGE_SMEM>>>(
            eRowS, eColS, E, x, hA, hB,
            m_w1 + (size_t)i*32896 + 32768, m_b1 + i*128,
            wtf + OFF_MW2 + i*16384, m_b2 + i*128,
            wtf + OFF_CW1 + i*16384, c_b1 + i*128, c_w2 + i*128,
            agg, cup);
        const uint32_t* WaN = (i < 3) ? (wtf + OFF_MW1A + (i+1)*16384) : (wtf + OFF_EMW1A);
        const uint32_t* WbN = (i < 3) ? (wtf + OFF_MW1B + (i+1)*16384) : (wtf + OFF_EMW1B);
        float* epsZ = (i == 3) ? eps : nullptr;   // zero eps just before edge_eps
        node_mlp_ln_proj<<<gN, NT, LN_SMEM>>>(agg,
            wtf + OFF_NW1A + i*16384, wtf + OFF_NW1B + i*16384, n_b1 + i*128,
            wtf + OFF_NW2 + i*16384, n_b2 + i*128,
            ln_g + i*128, ln_b + i*128, h, x, cup, deg,
            WaN, WbN, hA, hB, epsZ, n);
    }

    edge_eps_mma<<<gE, NT, EDGE_SMEM>>>(
        eRowS, eColS, E, x, hA, hB,
        em_w1 + 32768, em_b1,
        wtf + OFF_EMW2, em_b2, wtf + OFF_ECW1, ec_b1, ec_w2, ec_b2, eps);
    gemm_eps<<<gN, NT, EPS_SMEM>>>(h, wtf + OFF_EHW1, x,
        eh_w1 + 128*128, eh_b1, eh_w2, eh_b2, eps, n);

    pack_kernel<<<(n*134 + 255)/256, 256>>>(h, x, eps, (float*)d_out, n);
}